// round 8
// baseline (speedup 1.0000x reference)
#include <cuda_runtime.h>
#include <cuda_fp16.h>
#include <cstdint>
#include <math.h>

// Problem constants
#define BATCH 2
#define SEQ   2048
#define EMB   2048
#define NH    16
#define HDIM  128
#define E3    6144

#define SM_SCALE 0.08838834764831845f

// ---------------------------------------------------------------------------
// Scratch (__device__ globals; allocation-free rule)
// ---------------------------------------------------------------------------
__device__ float  g_qkv[(size_t)BATCH * SEQ * E3];                 // 96 MB fp32

__device__ __half g_xh[(size_t)BATCH * SEQ * EMB];
__device__ __half g_xl[(size_t)BATCH * SEQ * EMB];
__device__ __half g_wah[(size_t)E3 * EMB];                         // W_attn^T hi
__device__ __half g_qkh[(size_t)BATCH * SEQ * E3];                 // q hi | k hi
__device__ __half g_qkl[(size_t)BATCH * SEQ * E3];                 // q lo (k unused)
__device__ __half g_vth[(size_t)BATCH * NH * HDIM * SEQ];          // V^T hi
__device__ __half g_yh[(size_t)BATCH * SEQ * EMB];
__device__ __half g_yl[(size_t)BATCH * SEQ * EMB];
__device__ __half g_wph[(size_t)EMB * EMB];                        // W_proj^T hi

// ---------------------------------------------------------------------------
// PTX helpers (arch-generic: cp.async, ldmatrix, mma.sync)
// ---------------------------------------------------------------------------
__device__ __forceinline__ uint32_t smem_u32(const void* p) {
    uint32_t a;
    asm("{ .reg .u64 t; cvta.to.shared.u64 t, %1; cvt.u32.u64 %0, t; }"
        : "=r"(a) : "l"(p));
    return a;
}
#define CP16(dst, src) \
    asm volatile("cp.async.cg.shared.global [%0], [%1], 16;" :: "r"(dst), "l"(src))
#define CP_COMMIT() asm volatile("cp.async.commit_group;" ::: "memory")
#define CP_WAIT0()  asm volatile("cp.async.wait_group 0;" ::: "memory")
#define CP_WAIT1()  asm volatile("cp.async.wait_group 1;" ::: "memory")
#define CP_WAIT2()  asm volatile("cp.async.wait_group 2;" ::: "memory")

__device__ __forceinline__ void ldsm_x4(uint32_t* r, uint32_t a) {
    asm volatile("ldmatrix.sync.aligned.m8n8.x4.shared.b16 {%0,%1,%2,%3}, [%4];"
        : "=r"(r[0]), "=r"(r[1]), "=r"(r[2]), "=r"(r[3]) : "r"(a));
}
__device__ __forceinline__ void mma16816h(float* d, const uint32_t* a,
                                          const uint32_t* b) {
    asm volatile(
        "mma.sync.aligned.m16n8k16.row.col.f32.f16.f16.f32 "
        "{%0,%1,%2,%3}, {%4,%5,%6,%7}, {%8,%9}, {%0,%1,%2,%3};"
        : "+f"(d[0]), "+f"(d[1]), "+f"(d[2]), "+f"(d[3])
        : "r"(a[0]), "r"(a[1]), "r"(a[2]), "r"(a[3]), "r"(b[0]), "r"(b[1]));
}

// SMEM sub-tile: 128 rows x 32 fp16 = 64B rows, XOR swizzle (no padding).
#define ROW_B  64
#define TILE_B 8192

// ---------------------------------------------------------------------------
// Generic NT fp16 tensor-core GEMM: C = scale * (A @ B^T) + bias (fp32 out)
// 2 products: Ah*Bh + Al*Bh (= A * Bh; corrections on A side only).
// Tile 128x128, BK=32, 4-stage cp.async (WAIT2), 8 warps (2x4), 2 CTAs/SM.
// ---------------------------------------------------------------------------
#define GSTAGES 4
__global__ void __launch_bounds__(256, 2) gemm_f16(
    const __half* __restrict__ Ah, const __half* __restrict__ Al,
    const __half* __restrict__ Bh,
    float* __restrict__ C, const float* __restrict__ bias, float scale,
    int K, int lda, int ldb, int ldc)
{
    extern __shared__ char smem[];
    __shared__ float s_bias[128];
    constexpr uint32_t STB = 3 * TILE_B;   // stage bytes (Ah, Al, Bh)

    const int tid  = threadIdx.x;
    const int wid  = tid >> 5, lane = tid & 31;
    const int wm   = wid & 1;
    const int wn   = wid >> 1;
    const long long bm = (long long)blockIdx.y * 128;
    const long long bn = (long long)blockIdx.x * 128;

    const uint32_t sb = smem_u32(smem);

    if (tid < 128) s_bias[tid] = bias ? bias[bn + tid] : 0.0f;

    const int r0 = tid >> 2;
    const int cc = tid & 3;
    const uint32_t swsel = (uint32_t)((r0 & 3) ^ ((r0 >> 2) & 1));
    const uint32_t d0 = (uint32_t)r0 * ROW_B + ((cc ^ swsel) << 4);
    const uint32_t d1 = d0 + 64 * ROW_B;

    const __half* pAh0 = Ah + (bm + r0) * (long long)lda + cc * 8;
    const __half* pAh1 = pAh0 + 64LL * lda;
    const __half* pAl0 = Al + (bm + r0) * (long long)lda + cc * 8;
    const __half* pAl1 = pAl0 + 64LL * lda;
    const __half* pBh0 = Bh + (bn + r0) * (long long)ldb + cc * 8;
    const __half* pBh1 = pBh0 + 64LL * ldb;

    const int nt = K >> 5;

#define ISSUE_STAGE(st)                                              \
    do {                                                             \
        CP16((st) + 0 * TILE_B + d0, pAh0);                          \
        CP16((st) + 0 * TILE_B + d1, pAh1);                          \
        CP16((st) + 1 * TILE_B + d0, pAl0);                          \
        CP16((st) + 1 * TILE_B + d1, pAl1);                          \
        CP16((st) + 2 * TILE_B + d0, pBh0);                          \
        CP16((st) + 2 * TILE_B + d1, pBh1);                          \
        pAh0 += 32; pAh1 += 32; pAl0 += 32; pAl1 += 32;              \
        pBh0 += 32; pBh1 += 32;                                      \
    } while (0)

    // prefetch stages 0,1,2
    ISSUE_STAGE(sb);
    CP_COMMIT();
    ISSUE_STAGE(sb + STB);
    CP_COMMIT();
    ISSUE_STAGE(sb + 2 * STB);
    CP_COMMIT();

    float acc[4][4][4];
    #pragma unroll
    for (int i = 0; i < 4; ++i)
        #pragma unroll
        for (int j = 0; j < 4; ++j)
            #pragma unroll
            for (int k = 0; k < 4; ++k) acc[i][j][k] = 0.f;

    const int row_a = wm * 64 + (lane & 15);
    const uint32_t sa = (uint32_t)((row_a & 3) ^ ((row_a >> 2) & 1));
    const uint32_t a_base =
        (uint32_t)row_a * ROW_B + ((((uint32_t)lane >> 4) ^ sa) << 4);
    const int row_b = wn * 32 + ((lane >> 4) << 3) + (lane & 7);
    const uint32_t sbw = (uint32_t)((row_b & 3) ^ ((row_b >> 2) & 1));
    const uint32_t b_base =
        (uint32_t)row_b * ROW_B + (((((uint32_t)lane >> 3) & 1) ^ sbw) << 4);

    uint32_t cur_st = sb;                    // stage t % 4
    uint32_t iss_st = sb + 3 * STB;          // stage (t+3) % 4

    for (int t = 0; t < nt; ++t) {
        CP_WAIT2();
        __syncthreads();

        if (t + 3 < nt) ISSUE_STAGE(iss_st);
        CP_COMMIT();

        const uint32_t pAh = cur_st, pAl = cur_st + TILE_B,
                       pBh = cur_st + 2 * TILE_B;

        #pragma unroll
        for (int k16 = 0; k16 < 2; ++k16) {
            const uint32_t kx = (uint32_t)(k16 << 5);
            uint32_t fBh[2][4];
            #pragma unroll
            for (int bt = 0; bt < 2; ++bt)
                ldsm_x4(fBh[bt], pBh + ((b_base + bt * (16 * ROW_B)) ^ kx));
            #pragma unroll
            for (int mt = 0; mt < 4; ++mt) {
                uint32_t fAh[4], fAl[4];
                ldsm_x4(fAh, pAh + ((a_base + mt * (16 * ROW_B)) ^ kx));
                ldsm_x4(fAl, pAl + ((a_base + mt * (16 * ROW_B)) ^ kx));
                #pragma unroll
                for (int n8 = 0; n8 < 4; ++n8) {
                    const uint32_t* bh = &fBh[n8 >> 1][(n8 & 1) << 1];
                    mma16816h(acc[mt][n8], fAh, bh);
                    mma16816h(acc[mt][n8], fAl, bh);
                }
            }
        }

        uint32_t nxt = cur_st + STB;
        if (nxt >= sb + GSTAGES * STB) nxt = sb;
        cur_st = nxt;
        nxt = iss_st + STB;
        if (nxt >= sb + GSTAGES * STB) nxt = sb;
        iss_st = nxt;
    }
#undef ISSUE_STAGE

    #pragma unroll
    for (int mt = 0; mt < 4; ++mt) {
        const long long r = bm + wm * 64 + mt * 16 + (lane >> 2);
        float* row0 = C + r * ldc + bn + wn * 32;
        float* row1 = row0 + 8LL * ldc;
        #pragma unroll
        for (int n8 = 0; n8 < 4; ++n8) {
            const int c = n8 * 8 + ((lane & 3) << 1);
            const float b0 = s_bias[wn * 32 + c];
            const float b1 = s_bias[wn * 32 + c + 1];
            float2 v0, v1;
            v0.x = acc[mt][n8][0] * scale + b0;
            v0.y = acc[mt][n8][1] * scale + b1;
            v1.x = acc[mt][n8][2] * scale + b0;
            v1.y = acc[mt][n8][3] * scale + b1;
            *(float2*)(row0 + c) = v0;
            *(float2*)(row1 + c) = v1;
        }
    }
}

// ---------------------------------------------------------------------------
// exp + pack 4 fp32 -> fp16 hi/lo A-fragments, accumulate row sums
// ---------------------------------------------------------------------------
__device__ __forceinline__ void exp_pack4(const float* s, float& lsum0,
                                          float& lsum1, uint32_t* ph,
                                          uint32_t* pl)
{
    const float e0 = __expf(s[0] * SM_SCALE);
    const float e1 = __expf(s[1] * SM_SCALE);
    const float e2 = __expf(s[2] * SM_SCALE);
    const float e3 = __expf(s[3] * SM_SCALE);
    lsum0 += e0 + e1;
    lsum1 += e2 + e3;
    uint32_t h01, h23;
    asm("cvt.rn.f16x2.f32 %0, %1, %2;" : "=r"(h01) : "f"(e1), "f"(e0));
    asm("cvt.rn.f16x2.f32 %0, %1, %2;" : "=r"(h23) : "f"(e3), "f"(e2));
    const __half2 H01 = *(const __half2*)&h01;
    const __half2 H23 = *(const __half2*)&h23;
    const float r0 = e0 - __low2float(H01);
    const float r1 = e1 - __high2float(H01);
    const float r2 = e2 - __low2float(H23);
    const float r3 = e3 - __high2float(H23);
    uint32_t l01, l23;
    asm("cvt.rn.f16x2.f32 %0, %1, %2;" : "=r"(l01) : "f"(r1), "f"(r0));
    asm("cvt.rn.f16x2.f32 %0, %1, %2;" : "=r"(l23) : "f"(r3), "f"(r2));
    ph[0] = h01; ph[1] = h23;
    pl[0] = l01; pl[1] = l23;
}

// ---------------------------------------------------------------------------
// Fused flash attention, fp16, 2-product. Per-chunk fused S/exp/PV pipeline:
// for each 16-kv-col chunk c: S_c (32 MMA) -> exp_c -> PV_c (32 MMA).
// Chunks are independent -> tensor pipe stays fed through the exp blocks.
// SMEM: Qh|Ql (64K) + K0|K1 (32K each) + V0|V1 (32K each) = 192 KB.
// ---------------------------------------------------------------------------
#define FA_SMEM (192 * 1024)

__global__ void __launch_bounds__(256) flash_kernel()
{
    extern __shared__ char smem[];
    const int z = blockIdx.y;
    const int b = z >> 4, h = z & 15;
    const int bq = blockIdx.x * 128;
    const int tid = threadIdx.x;
    const int wid = tid >> 5, lane = tid & 31;

    const uint32_t sb  = smem_u32(smem);
    const uint32_t BQh = sb, BQl = sb + 32768;
    const uint32_t K0 = sb + 65536,  K1 = sb + 98304;
    const uint32_t V0 = sb + 131072, V1 = sb + 163840;

    const int r0 = tid >> 2;
    const int cc = tid & 3;
    const uint32_t swsel = (uint32_t)((r0 & 3) ^ ((r0 >> 2) & 1));
    const uint32_t d0 = (uint32_t)r0 * 64 + ((cc ^ swsel) << 4);
    const uint32_t d1 = d0 + 64 * 64;

    const long long zq = (long long)b * SEQ * E3 + (long long)h * HDIM;
    const __half* Qh = g_qkh + zq;
    const __half* Ql = g_qkl + zq;
    const __half* Kh = Qh + EMB;
    const __half* Vh = g_vth + (long long)z * HDIM * SEQ;

#define FA_LD1(buf, G, rowbase, ldx, colbase)                              \
    do { _Pragma("unroll")                                                 \
        for (int kc = 0; kc < 4; ++kc) {                                   \
            const long long off = ((long long)(rowbase) + r0) * (ldx)      \
                                  + (colbase) + kc * 32 + cc * 8;          \
            CP16((buf) + kc * 8192 + d0, (G) + off);                       \
            CP16((buf) + kc * 8192 + d1, (G) + off + 64LL * (ldx));        \
        }                                                                  \
    } while (0)

    // prologue: Q (hi+lo), K0, V0
    FA_LD1(BQh, Qh, bq, E3, 0);
    FA_LD1(BQl, Ql, bq, E3, 0);
    CP_COMMIT();
    FA_LD1(K0, Kh, 0, E3, 0);
    CP_COMMIT();
    FA_LD1(V0, Vh, 0, SEQ, 0);
    CP_COMMIT();

    CP_WAIT2();          // Q resident
    __syncthreads();

    const int row_a = wid * 16 + (lane & 15);
    const uint32_t swA = (uint32_t)((row_a & 3) ^ ((row_a >> 2) & 1));
    const uint32_t a_base =
        (uint32_t)row_a * 64 + ((((uint32_t)lane >> 4) ^ swA) << 4);
    uint32_t qfh[8][4], qfl[8][4];
    #pragma unroll
    for (int k16 = 0; k16 < 8; ++k16) {
        const uint32_t ad = (uint32_t)(k16 >> 1) * 8192 +
                            (a_base ^ ((uint32_t)(k16 & 1) << 5));
        ldsm_x4(qfh[k16], BQh + ad);
        ldsm_x4(qfl[k16], BQl + ad);
    }

    const int row_b = ((lane >> 4) << 3) + (lane & 7);
    const uint32_t swB = (uint32_t)((row_b & 3) ^ ((row_b >> 2) & 1));
    const uint32_t b_base =
        (uint32_t)row_b * 64 + (((((uint32_t)lane >> 3) & 1) ^ swB) << 4);

    float yacc[16][4];
    #pragma unroll
    for (int i = 0; i < 16; ++i)
        #pragma unroll
        for (int j = 0; j < 4; ++j) yacc[i][j] = 0.f;
    float lsum0 = 0.f, lsum1 = 0.f;

    for (int i = 0; i < 16; ++i) {
        const uint32_t curK = (i & 1) ? K1 : K0;
        const uint32_t curV = (i & 1) ? V1 : V0;

        CP_WAIT0();          // K_i, V_i resident
        __syncthreads();     // everyone done with buffers of iter i-1

        if (i < 15) {
            FA_LD1((i & 1) ? K0 : K1, Kh, 128 * (i + 1), E3, 0);
            CP_COMMIT();
            FA_LD1((i & 1) ? V0 : V1, Vh, 0, SEQ, 128 * (i + 1));
            CP_COMMIT();
        }

        // ---- fused per-chunk: S_c -> exp_c -> PV_c (chunks independent) ----
        #pragma unroll
        for (int c = 0; c < 8; ++c) {
            float s0[4] = {0.f, 0.f, 0.f, 0.f};
            float s1[4] = {0.f, 0.f, 0.f, 0.f};
            #pragma unroll
            for (int k16 = 0; k16 < 8; ++k16) {
                uint32_t fh[4];
                const uint32_t ad = (uint32_t)(k16 >> 1) * 8192 +
                    ((b_base + (uint32_t)c * 1024u) ^ ((uint32_t)(k16 & 1) << 5));
                ldsm_x4(fh, curK + ad);
                mma16816h(s0, qfh[k16], fh);
                mma16816h(s1, qfh[k16], fh + 2);
                mma16816h(s0, qfl[k16], fh);
                mma16816h(s1, qfl[k16], fh + 2);
            }
            uint32_t ph[4], pl[4];
            exp_pack4(s0, lsum0, lsum1, &ph[0], &pl[0]);
            exp_pack4(s1, lsum0, lsum1, &ph[2], &pl[2]);
            #pragma unroll
            for (int nb = 0; nb < 8; ++nb) {
                uint32_t fv[4];
                const uint32_t ad = (uint32_t)(c >> 1) * 8192 +
                    ((b_base + (uint32_t)nb * 1024u) ^ ((uint32_t)(c & 1) << 5));
                ldsm_x4(fv, curV + ad);
                mma16816h(yacc[2 * nb],     ph, fv);
                mma16816h(yacc[2 * nb + 1], ph, fv + 2);
                mma16816h(yacc[2 * nb],     pl, fv);
                mma16816h(yacc[2 * nb + 1], pl, fv + 2);
            }
        }
    }
#undef FA_LD1

    // ---- normalize + split + store ----
    lsum0 += __shfl_xor_sync(0xffffffffu, lsum0, 1);
    lsum0 += __shfl_xor_sync(0xffffffffu, lsum0, 2);
    lsum1 += __shfl_xor_sync(0xffffffffu, lsum1, 1);
    lsum1 += __shfl_xor_sync(0xffffffffu, lsum1, 2);
    const float inv0 = 1.0f / lsum0;
    const float inv1 = 1.0f / lsum1;

    const int q0 = bq + wid * 16 + (lane >> 2);
    const long long ob = (long long)b * SEQ * EMB + (long long)h * HDIM;
    #pragma unroll
    for (int T = 0; T < 16; ++T) {
        const int dcol = T * 8 + ((lane & 3) << 1);
        const float v0 = yacc[T][0] * inv0;
        const float v1 = yacc[T][1] * inv0;
        const float v2 = yacc[T][2] * inv1;
        const float v3 = yacc[T][3] * inv1;
        const __half h0 = __float2half_rn(v0);
        const __half h1 = __float2half_rn(v1);
        const __half h2 = __float2half_rn(v2);
        const __half h3 = __float2half_rn(v3);
        __half2 hh0, ll0, hh1, ll1;
        hh0.x = h0; hh0.y = h1;
        ll0.x = __float2half_rn(v0 - __half2float(h0));
        ll0.y = __float2half_rn(v1 - __half2float(h1));
        hh1.x = h2; hh1.y = h3;
        ll1.x = __float2half_rn(v2 - __half2float(h2));
        ll1.y = __float2half_rn(v3 - __half2float(h3));
        const long long o0 = ob + (long long)q0 * EMB + dcol;
        const long long o1 = o0 + 8LL * EMB;
        *(__half2*)(g_yh + o0) = hh0;
        *(__half2*)(g_yl + o0) = ll0;
        *(__half2*)(g_yh + o1) = hh1;
        *(__half2*)(g_yl + o1) = ll1;
    }
}

// ---------------------------------------------------------------------------
// fp32 -> (hi, lo) fp16 split, flat, 4 elems/thread
// ---------------------------------------------------------------------------
struct h4 { __half x, y, z, w; };

__global__ void __launch_bounds__(256) split_kernel(
    const float* __restrict__ s, __half* __restrict__ h,
    __half* __restrict__ l, int n4)
{
    const int i = blockIdx.x * 256 + threadIdx.x;
    if (i >= n4) return;
    const float4 v = ((const float4*)s)[i];
    h4 hh, lo;
    hh.x = __float2half_rn(v.x); lo.x = __float2half_rn(v.x - __half2float(hh.x));
    hh.y = __float2half_rn(v.y); lo.y = __float2half_rn(v.y - __half2float(hh.y));
    hh.z = __float2half_rn(v.z); lo.z = __float2half_rn(v.z - __half2float(hh.z));
    hh.w = __float2half_rn(v.w); lo.w = __float2half_rn(v.w - __half2float(hh.w));
    ((h4*)h)[i] = hh;
    ((h4*)l)[i] = lo;
}

// ---------------------------------------------------------------------------
// Transpose (hi only): src [K,N] fp32 row-major -> dst [N,K] fp16
// ---------------------------------------------------------------------------
__global__ void __launch_bounds__(256) tsplit_kernel(
    const float* __restrict__ s, __half* __restrict__ h, int K, int N)
{
    __shared__ float tile[32][33];
    const int tx = threadIdx.x, ty = threadIdx.y;
    const int n0 = blockIdx.x * 32, k0 = blockIdx.y * 32;
    #pragma unroll
    for (int j = 0; j < 32; j += 8)
        tile[ty + j][tx] = s[(long long)(k0 + ty + j) * N + n0 + tx];
    __syncthreads();
    #pragma unroll
    for (int j = 0; j < 32; j += 8) {
        const float v = tile[tx][ty + j];
        const long long o = (long long)(n0 + ty + j) * K + k0 + tx;
        h[o] = __float2half_rn(v);
    }
}

// ---------------------------------------------------------------------------
// V transpose (hi only): qkv[b,l,2E+h*128+d] -> vth[(b*16+h)*128+d][l]
// ---------------------------------------------------------------------------
__global__ void __launch_bounds__(256) vtrans_kernel()
{
    __shared__ float tile[32][33];
    const int tx = threadIdx.x, ty = threadIdx.y;
    const int z = blockIdx.z, b = z >> 4, h = z & 15;
    const int l0 = blockIdx.x * 32, d0 = blockIdx.y * 32;
    const float* src = g_qkv + (long long)b * SEQ * E3 + 2 * EMB + h * HDIM;
    #pragma unroll
    for (int j = 0; j < 32; j += 8)
        tile[ty + j][tx] = src[(long long)(l0 + ty + j) * E3 + d0 + tx];
    __syncthreads();
    #pragma unroll
    for (int j = 0; j < 32; j += 8) {
        const float v = tile[tx][ty + j];
        const long long o = ((long long)z * HDIM + d0 + ty + j) * SEQ + l0 + tx;
        g_vth[o] = __float2half_rn(v);
    }
}

// ---------------------------------------------------------------------------
// RoPE + split: q -> fp16 hi/lo; k -> fp16 hi only
// ---------------------------------------------------------------------------
__global__ void __launch_bounds__(256) rope_split_kernel(const int* __restrict__ pos)
{
    const int idx = blockIdx.x * 256 + threadIdx.x;
    const int j  = idx & 63;
    const int h  = (idx >> 6) & 15;
    const int bl = idx >> 10;
    const float p = (float)pos[bl];
    const float invf = expf(-(float)j * 0.14391156831212787f);
    float s, c;
    sincosf(p * invf, &s, &c);
    const float* base = g_qkv + (long long)bl * E3 + h * HDIM;
    const float q0 = base[j],       q1 = base[64 + j];
    const float k0 = base[EMB + j], k1 = base[EMB + 64 + j];
    const float rq0 = q0 * c - q1 * s;
    const float rq1 = q1 * c + q0 * s;
    const float rk0 = k0 * c - k1 * s;
    const float rk1 = k1 * c + k0 * s;

    const long long o = (long long)bl * E3 + h * HDIM;
    __half hv;
    hv = __float2half_rn(rq0);
    g_qkh[o + j] = hv;
    g_qkl[o + j] = __float2half_rn(rq0 - __half2float(hv));
    hv = __float2half_rn(rq1);
    g_qkh[o + 64 + j] = hv;
    g_qkl[o + 64 + j] = __float2half_rn(rq1 - __half2float(hv));
    g_qkh[o + EMB + j]      = __float2half_rn(rk0);
    g_qkh[o + EMB + 64 + j] = __float2half_rn(rk1);
}

// ---------------------------------------------------------------------------
// Launch sequence
// ---------------------------------------------------------------------------
extern "C" void kernel_launch(void* const* d_in, const int* in_sizes, int n_in,
                              void* d_out, int out_size)
{
    const float* x      = (const float*)d_in[0];
    const int*   pos    = (const int*)  d_in[1];
    const float* W_attn = (const float*)d_in[2];
    const float* b_attn = (const float*)d_in[3];
    const float* W_proj = (const float*)d_in[4];
    const float* b_proj = (const float*)d_in[5];
    float* out = (float*)d_out;

    float* qkv;
    __half *xh, *xl, *wah, *yh, *yl, *wph;
    cudaGetSymbolAddress((void**)&qkv, g_qkv);
    cudaGetSymbolAddress((void**)&xh,  g_xh);  cudaGetSymbolAddress((void**)&xl,  g_xl);
    cudaGetSymbolAddress((void**)&wah, g_wah);
    cudaGetSymbolAddress((void**)&yh,  g_yh);  cudaGetSymbolAddress((void**)&yl,  g_yl);
    cudaGetSymbolAddress((void**)&wph, g_wph);

    cudaFuncSetAttribute(gemm_f16,
                         cudaFuncAttributeMaxDynamicSharedMemorySize,
                         GSTAGES * 3 * TILE_B);
    cudaFuncSetAttribute(flash_kernel,
                         cudaFuncAttributeMaxDynamicSharedMemorySize, FA_SMEM);

    const dim3 tb(32, 8, 1);

    // 0. input conversions (fp16; A-side hi/lo, weights hi only)
    split_kernel<<<(BATCH * SEQ * EMB / 4 + 255) / 256, 256>>>(x, xh, xl,
                                                               BATCH * SEQ * EMB / 4);
    tsplit_kernel<<<dim3(E3 / 32, EMB / 32, 1), tb>>>(W_attn, wah, EMB, E3);
    tsplit_kernel<<<dim3(EMB / 32, EMB / 32, 1), tb>>>(W_proj, wph, EMB, EMB);

    // 1. qkv = x @ W_attn + b (2-product): M=4096, N=6144, K=2048
    gemm_f16<<<dim3(E3 / 128, (BATCH * SEQ) / 128, 1), 256, GSTAGES * 3 * TILE_B>>>(
        xh, xl, wah, qkv, b_attn, 1.0f, EMB, EMB, EMB, E3);

    // 2. RoPE + split q (hi/lo), k (hi)
    rope_split_kernel<<<(BATCH * SEQ * NH * 64) / 256, 256>>>(pos);

    // 3. V transpose (hi only)
    vtrans_kernel<<<dim3(SEQ / 32, HDIM / 32, BATCH * NH), tb>>>();

    // 4. fused attention (2-product) -> yh/yl
    flash_kernel<<<dim3(SEQ / 128, BATCH * NH, 1), 256, FA_SMEM>>>();

    // 5. out = y @ W_proj + b (2-product): M=4096, N=2048, K=2048
    gemm_f16<<<dim3(EMB / 128, (BATCH * SEQ) / 128, 1), 256, GSTAGES * 3 * TILE_B>>>(
        yh, yl, wph, out, b_proj, 1.0f, EMB, EMB, EMB, EMB);
}

// round 9
// speedup vs baseline: 1.0015x; 1.0015x over previous
#include <cuda_runtime.h>
#include <cuda_fp16.h>
#include <cstdint>
#include <math.h>

// Problem constants
#define BATCH 2
#define SEQ   2048
#define EMB   2048
#define NH    16
#define HDIM  128
#define E3    6144

#define SM_SCALE 0.08838834764831845f

// ---------------------------------------------------------------------------
// Scratch (__device__ globals; allocation-free rule)
// ---------------------------------------------------------------------------
__device__ __half g_xh[(size_t)BATCH * SEQ * EMB];
__device__ __half g_xl[(size_t)BATCH * SEQ * EMB];
__device__ __half g_wah[(size_t)E3 * EMB];                         // W_attn^T hi
__device__ __half g_qkh[(size_t)BATCH * SEQ * E3];                 // q hi | k hi
__device__ __half g_qkl[(size_t)BATCH * SEQ * E3];                 // q lo
__device__ __half g_vth[(size_t)BATCH * NH * HDIM * SEQ];          // V^T hi
__device__ __half g_yh[(size_t)BATCH * SEQ * EMB];
__device__ __half g_yl[(size_t)BATCH * SEQ * EMB];
__device__ __half g_wph[(size_t)EMB * EMB];                        // W_proj^T hi

// ---------------------------------------------------------------------------
// PTX helpers (arch-generic: cp.async, ldmatrix, mma.sync)
// ---------------------------------------------------------------------------
__device__ __forceinline__ uint32_t smem_u32(const void* p) {
    uint32_t a;
    asm("{ .reg .u64 t; cvta.to.shared.u64 t, %1; cvt.u32.u64 %0, t; }"
        : "=r"(a) : "l"(p));
    return a;
}
#define CP16(dst, src) \
    asm volatile("cp.async.cg.shared.global [%0], [%1], 16;" :: "r"(dst), "l"(src))
#define CP_COMMIT() asm volatile("cp.async.commit_group;" ::: "memory")
#define CP_WAIT0()  asm volatile("cp.async.wait_group 0;" ::: "memory")
#define CP_WAIT1()  asm volatile("cp.async.wait_group 1;" ::: "memory")
#define CP_WAIT2()  asm volatile("cp.async.wait_group 2;" ::: "memory")

__device__ __forceinline__ void ldsm_x4(uint32_t* r, uint32_t a) {
    asm volatile("ldmatrix.sync.aligned.m8n8.x4.shared.b16 {%0,%1,%2,%3}, [%4];"
        : "=r"(r[0]), "=r"(r[1]), "=r"(r[2]), "=r"(r[3]) : "r"(a));
}
__device__ __forceinline__ void mma16816h(float* d, const uint32_t* a,
                                          const uint32_t* b) {
    asm volatile(
        "mma.sync.aligned.m16n8k16.row.col.f32.f16.f16.f32 "
        "{%0,%1,%2,%3}, {%4,%5,%6,%7}, {%8,%9}, {%0,%1,%2,%3};"
        : "+f"(d[0]), "+f"(d[1]), "+f"(d[2]), "+f"(d[3])
        : "r"(a[0]), "r"(a[1]), "r"(a[2]), "r"(a[3]), "r"(b[0]), "r"(b[1]));
}

// SMEM sub-tile: 128 rows x 32 fp16 = 64B rows, XOR swizzle (no padding).
#define ROW_B  64
#define TILE_B 8192
#define STB    (3 * TILE_B)          // stage bytes (Ah, Al, Bh)
#define GSMEM  (3 * STB)             // 73728: 3 stages; also >= 128*129*4 staging

// ===========================================================================
// Shared GEMM mainloop (2 products: A*Bh with A=Ah+Al): computes acc[4][4][4]
// ===========================================================================
#define GEMM_MAINLOOP(Ah, Al, Bh, K, lda, ldb)                               \
    const int r0 = tid >> 2;                                                 \
    const int cc = tid & 3;                                                  \
    const uint32_t swsel = (uint32_t)((r0 & 3) ^ ((r0 >> 2) & 1));           \
    const uint32_t d0 = (uint32_t)r0 * ROW_B + ((cc ^ swsel) << 4);          \
    const uint32_t d1 = d0 + 64 * ROW_B;                                     \
    const __half* pAh0 = (Ah) + (bm + r0) * (long long)(lda) + cc * 8;       \
    const __half* pAh1 = pAh0 + 64LL * (lda);                                \
    const __half* pAl0 = (Al) + (bm + r0) * (long long)(lda) + cc * 8;       \
    const __half* pAl1 = pAl0 + 64LL * (lda);                                \
    const __half* pBh0 = (Bh) + (bn + r0) * (long long)(ldb) + cc * 8;       \
    const __half* pBh1 = pBh0 + 64LL * (ldb);                                \
    const int nt = (K) >> 5;                                                 \
    ISSUE_STAGE(sb);                                                         \
    CP_COMMIT();                                                             \
    ISSUE_STAGE(sb + STB);                                                   \
    CP_COMMIT();                                                             \
    float acc[4][4][4];                                                      \
    _Pragma("unroll")                                                        \
    for (int i = 0; i < 4; ++i)                                              \
        _Pragma("unroll")                                                    \
        for (int j = 0; j < 4; ++j)                                          \
            _Pragma("unroll")                                                \
            for (int k = 0; k < 4; ++k) acc[i][j][k] = 0.f;                  \
    const int row_a = wm * 64 + (lane & 15);                                 \
    const uint32_t sa = (uint32_t)((row_a & 3) ^ ((row_a >> 2) & 1));        \
    const uint32_t a_base =                                                  \
        (uint32_t)row_a * ROW_B + ((((uint32_t)lane >> 4) ^ sa) << 4);       \
    const int row_b = wn * 32 + ((lane >> 4) << 3) + (lane & 7);             \
    const uint32_t sbw = (uint32_t)((row_b & 3) ^ ((row_b >> 2) & 1));       \
    const uint32_t b_base =                                                  \
        (uint32_t)row_b * ROW_B + (((((uint32_t)lane >> 3) & 1) ^ sbw) << 4);\
    uint32_t cur_st = sb;                                                    \
    uint32_t iss_st = sb + 2 * STB;                                          \
    for (int t = 0; t < nt; ++t) {                                           \
        CP_WAIT1();                                                          \
        __syncthreads();                                                     \
        if (t + 2 < nt) ISSUE_STAGE(iss_st);                                 \
        CP_COMMIT();                                                         \
        const uint32_t pAh = cur_st, pAl = cur_st + TILE_B,                  \
                       pBh = cur_st + 2 * TILE_B;                            \
        _Pragma("unroll")                                                    \
        for (int k16 = 0; k16 < 2; ++k16) {                                  \
            const uint32_t kx = (uint32_t)(k16 << 5);                        \
            uint32_t fBh[2][4];                                              \
            _Pragma("unroll")                                                \
            for (int bt = 0; bt < 2; ++bt)                                   \
                ldsm_x4(fBh[bt], pBh + ((b_base + bt * (16 * ROW_B)) ^ kx)); \
            _Pragma("unroll")                                                \
            for (int mt = 0; mt < 4; ++mt) {                                 \
                uint32_t fAh[4], fAl[4];                                     \
                ldsm_x4(fAh, pAh + ((a_base + mt * (16 * ROW_B)) ^ kx));     \
                ldsm_x4(fAl, pAl + ((a_base + mt * (16 * ROW_B)) ^ kx));     \
                _Pragma("unroll")                                            \
                for (int n8 = 0; n8 < 4; ++n8) {                             \
                    const uint32_t* bh = &fBh[n8 >> 1][(n8 & 1) << 1];       \
                    mma16816h(acc[mt][n8], fAh, bh);                         \
                    mma16816h(acc[mt][n8], fAl, bh);                         \
                }                                                            \
            }                                                                \
        }                                                                    \
        uint32_t nxt = cur_st + STB;                                         \
        if (nxt >= sb + 3 * STB) nxt = sb;                                   \
        cur_st = nxt;                                                        \
        nxt = iss_st + STB;                                                  \
        if (nxt >= sb + 3 * STB) nxt = sb;                                   \
        iss_st = nxt;                                                        \
    }

#define ISSUE_STAGE(st)                                              \
    do {                                                             \
        CP16((st) + 0 * TILE_B + d0, pAh0);                          \
        CP16((st) + 0 * TILE_B + d1, pAh1);                          \
        CP16((st) + 1 * TILE_B + d0, pAl0);                          \
        CP16((st) + 1 * TILE_B + d1, pAl1);                          \
        CP16((st) + 2 * TILE_B + d0, pBh0);                          \
        CP16((st) + 2 * TILE_B + d1, pBh1);                          \
        pAh0 += 32; pAh1 += 32; pAl0 += 32; pAl1 += 32;              \
        pBh0 += 32; pBh1 += 32;                                      \
    } while (0)

// ---------------------------------------------------------------------------
// Generic NT fp16 GEMM (proj): C = A @ Bh + bias (fp32 out)
// ---------------------------------------------------------------------------
__global__ void __launch_bounds__(256, 2) gemm_f16(
    const __half* __restrict__ Ah, const __half* __restrict__ Al,
    const __half* __restrict__ Bh,
    float* __restrict__ C, const float* __restrict__ bias,
    int K, int lda, int ldb, int ldc)
{
    extern __shared__ char smem[];
    __shared__ float s_bias[128];

    const int tid  = threadIdx.x;
    const int wid  = tid >> 5, lane = tid & 31;
    const int wm   = wid & 1;
    const int wn   = wid >> 1;
    const long long bm = (long long)blockIdx.y * 128;
    const long long bn = (long long)blockIdx.x * 128;
    const uint32_t sb = smem_u32(smem);

    if (tid < 128) s_bias[tid] = bias[bn + tid];

    GEMM_MAINLOOP(Ah, Al, Bh, K, lda, ldb)

    #pragma unroll
    for (int mt = 0; mt < 4; ++mt) {
        const long long r = bm + wm * 64 + mt * 16 + (lane >> 2);
        float* row0 = C + r * ldc + bn + wn * 32;
        float* row1 = row0 + 8LL * ldc;
        #pragma unroll
        for (int n8 = 0; n8 < 4; ++n8) {
            const int c = n8 * 8 + ((lane & 3) << 1);
            const float b0 = s_bias[wn * 32 + c];
            const float b1 = s_bias[wn * 32 + c + 1];
            float2 v0, v1;
            v0.x = acc[mt][n8][0] + b0;
            v0.y = acc[mt][n8][1] + b1;
            v1.x = acc[mt][n8][2] + b0;
            v1.y = acc[mt][n8][3] + b1;
            *(float2*)(row0 + c) = v0;
            *(float2*)(row1 + c) = v1;
        }
    }
}

// ---------------------------------------------------------------------------
// QKV GEMM with fused RoPE / V-transpose epilogue.
// Tile cols bn..bn+127 = exactly one head of q, k, or v.
//   q (bn<2048):      RoPE, write fp16 hi+lo to g_qkh/g_qkl
//   k (2048..4096):   RoPE, write fp16 hi to g_qkh
//   v (bn>=4096):     transpose, write fp16 hi to g_vth [(b,h),d,l]
// Epilogue stages the biased fp32 tile in smem (128x129) for the cross-warp
// (j, j+64) rotation pairs and the transpose.
// ---------------------------------------------------------------------------
__global__ void __launch_bounds__(256, 2) gemm_qkv(
    const __half* __restrict__ Ah, const __half* __restrict__ Al,
    const __half* __restrict__ Bh,
    const float* __restrict__ bias, const int* __restrict__ pos)
{
    extern __shared__ char smem[];
    __shared__ float s_bias[128];

    const int tid  = threadIdx.x;
    const int wid  = tid >> 5, lane = tid & 31;
    const int wm   = wid & 1;
    const int wn   = wid >> 1;
    const long long bm = (long long)blockIdx.y * 128;
    const long long bn = (long long)blockIdx.x * 128;
    const uint32_t sb = smem_u32(smem);

    if (tid < 128) s_bias[tid] = bias[bn + tid];

    GEMM_MAINLOOP(Ah, Al, Bh, EMB, EMB, EMB)

    // ---- stage biased fp32 tile into smem [128][129] ----
    __syncthreads();            // all warps done reading pipeline smem
    float* st = (float*)smem;
    #pragma unroll
    for (int mt = 0; mt < 4; ++mt) {
        const int rr = wm * 64 + mt * 16 + (lane >> 2);
        #pragma unroll
        for (int n8 = 0; n8 < 4; ++n8) {
            const int c = wn * 32 + n8 * 8 + ((lane & 3) << 1);
            const float b0 = s_bias[c], b1 = s_bias[c + 1];
            st[rr * 129 + c]           = acc[mt][n8][0] + b0;
            st[rr * 129 + c + 1]       = acc[mt][n8][1] + b1;
            st[(rr + 8) * 129 + c]     = acc[mt][n8][2] + b0;
            st[(rr + 8) * 129 + c + 1] = acc[mt][n8][3] + b1;
        }
    }
    __syncthreads();

    if (bn < 2 * EMB) {
        // ---- q or k head: RoPE ----
        const bool isq = (bn < EMB);
        #pragma unroll
        for (int it = 0; it < 32; ++it) {
            const int idx = it * 256 + tid;
            const int r = idx >> 6, j = idx & 63;
            const float v0 = st[r * 129 + j];
            const float v1 = st[r * 129 + j + 64];
            const float p = (float)pos[bm + r];
            const float invf = expf(-(float)j * 0.14391156831212787f);
            float sn, cs;
            sincosf(p * invf, &sn, &cs);
            const float rq0 = v0 * cs - v1 * sn;
            const float rq1 = v1 * cs + v0 * sn;
            const long long o = (bm + r) * (long long)E3 + bn;
            const __half h0 = __float2half_rn(rq0);
            const __half h1 = __float2half_rn(rq1);
            g_qkh[o + j]      = h0;
            g_qkh[o + j + 64] = h1;
            if (isq) {
                g_qkl[o + j]      = __float2half_rn(rq0 - __half2float(h0));
                g_qkl[o + j + 64] = __float2half_rn(rq1 - __half2float(h1));
            }
        }
    } else {
        // ---- v head: transpose to [(b,h), d, l] ----
        const int hh = (int)((bn - 2 * EMB) >> 7);
        const int bb = (int)(bm >> 11);
        const int lbase = (int)(bm & (SEQ - 1));
        const long long vbase =
            ((long long)(bb * NH + hh) * HDIM) * SEQ + lbase;
        #pragma unroll
        for (int it = 0; it < 64; ++it) {
            const int idx = it * 256 + tid;
            const int d = idx >> 7, l = idx & 127;
            g_vth[vbase + (long long)d * SEQ + l] =
                __float2half_rn(st[l * 129 + d]);
        }
    }
}

// ---------------------------------------------------------------------------
// exp + pack 4 fp32 -> fp16 hi/lo A-fragments, accumulate row sums
// ---------------------------------------------------------------------------
__device__ __forceinline__ void exp_pack4(const float* s, float& lsum0,
                                          float& lsum1, uint32_t* ph,
                                          uint32_t* pl)
{
    const float e0 = __expf(s[0] * SM_SCALE);
    const float e1 = __expf(s[1] * SM_SCALE);
    const float e2 = __expf(s[2] * SM_SCALE);
    const float e3 = __expf(s[3] * SM_SCALE);
    lsum0 += e0 + e1;
    lsum1 += e2 + e3;
    uint32_t h01, h23;
    asm("cvt.rn.f16x2.f32 %0, %1, %2;" : "=r"(h01) : "f"(e1), "f"(e0));
    asm("cvt.rn.f16x2.f32 %0, %1, %2;" : "=r"(h23) : "f"(e3), "f"(e2));
    const __half2 H01 = *(const __half2*)&h01;
    const __half2 H23 = *(const __half2*)&h23;
    const float r0 = e0 - __low2float(H01);
    const float r1 = e1 - __high2float(H01);
    const float r2 = e2 - __low2float(H23);
    const float r3 = e3 - __high2float(H23);
    uint32_t l01, l23;
    asm("cvt.rn.f16x2.f32 %0, %1, %2;" : "=r"(l01) : "f"(r1), "f"(r0));
    asm("cvt.rn.f16x2.f32 %0, %1, %2;" : "=r"(l23) : "f"(r3), "f"(r2));
    ph[0] = h01; ph[1] = h23;
    pl[0] = l01; pl[1] = l23;
}

// ---------------------------------------------------------------------------
// Fused flash attention, fp16, 2-product (R7 structure — measured best).
// SMEM: Qh|Ql (64K) + K0|K1 (32K each) + V0|V1 (32K each) = 192 KB.
// ---------------------------------------------------------------------------
#define FA_SMEM (192 * 1024)

__global__ void __launch_bounds__(256) flash_kernel()
{
    extern __shared__ char smem[];
    const int z = blockIdx.y;
    const int b = z >> 4, h = z & 15;
    const int bq = blockIdx.x * 128;
    const int tid = threadIdx.x;
    const int wid = tid >> 5, lane = tid & 31;

    const uint32_t sb  = smem_u32(smem);
    const uint32_t BQh = sb, BQl = sb + 32768;
    const uint32_t K0 = sb + 65536,  K1 = sb + 98304;
    const uint32_t V0 = sb + 131072, V1 = sb + 163840;

    const int r0 = tid >> 2;
    const int cc = tid & 3;
    const uint32_t swsel = (uint32_t)((r0 & 3) ^ ((r0 >> 2) & 1));
    const uint32_t d0 = (uint32_t)r0 * 64 + ((cc ^ swsel) << 4);
    const uint32_t d1 = d0 + 64 * 64;

    const long long zq = (long long)b * SEQ * E3 + (long long)h * HDIM;
    const __half* Qh = g_qkh + zq;
    const __half* Ql = g_qkl + zq;
    const __half* Kh = Qh + EMB;
    const __half* Vh = g_vth + (long long)z * HDIM * SEQ;

#define FA_LD1(buf, G, rowbase, ldx, colbase)                              \
    do { _Pragma("unroll")                                                 \
        for (int kc = 0; kc < 4; ++kc) {                                   \
            const long long off = ((long long)(rowbase) + r0) * (ldx)      \
                                  + (colbase) + kc * 32 + cc * 8;          \
            CP16((buf) + kc * 8192 + d0, (G) + off);                       \
            CP16((buf) + kc * 8192 + d1, (G) + off + 64LL * (ldx));        \
        }                                                                  \
    } while (0)

    // prologue: Q (hi+lo), K0, V0
    FA_LD1(BQh, Qh, bq, E3, 0);
    FA_LD1(BQl, Ql, bq, E3, 0);
    CP_COMMIT();
    FA_LD1(K0, Kh, 0, E3, 0);
    CP_COMMIT();
    FA_LD1(V0, Vh, 0, SEQ, 0);
    CP_COMMIT();

    CP_WAIT2();          // Q resident
    __syncthreads();

    const int row_a = wid * 16 + (lane & 15);
    const uint32_t swA = (uint32_t)((row_a & 3) ^ ((row_a >> 2) & 1));
    const uint32_t a_base =
        (uint32_t)row_a * 64 + ((((uint32_t)lane >> 4) ^ swA) << 4);
    uint32_t qfh[8][4], qfl[8][4];
    #pragma unroll
    for (int k16 = 0; k16 < 8; ++k16) {
        const uint32_t ad = (uint32_t)(k16 >> 1) * 8192 +
                            (a_base ^ ((uint32_t)(k16 & 1) << 5));
        ldsm_x4(qfh[k16], BQh + ad);
        ldsm_x4(qfl[k16], BQl + ad);
    }

    const int row_b = ((lane >> 4) << 3) + (lane & 7);
    const uint32_t swB = (uint32_t)((row_b & 3) ^ ((row_b >> 2) & 1));
    const uint32_t b_base =
        (uint32_t)row_b * 64 + (((((uint32_t)lane >> 3) & 1) ^ swB) << 4);

    float yacc[16][4];
    #pragma unroll
    for (int i = 0; i < 16; ++i)
        #pragma unroll
        for (int j = 0; j < 4; ++j) yacc[i][j] = 0.f;
    float lsum0 = 0.f, lsum1 = 0.f;

    for (int i = 0; i < 16; ++i) {
        const uint32_t curK = (i & 1) ? K1 : K0;
        const uint32_t curV = (i & 1) ? V1 : V0;

        CP_WAIT0();          // K_i, V_i resident
        __syncthreads();     // everyone done with buffers of iter i-1

        if (i < 15) {
            FA_LD1((i & 1) ? K0 : K1, Kh, 128 * (i + 1), E3, 0);
            CP_COMMIT();
            FA_LD1((i & 1) ? V0 : V1, Vh, 0, SEQ, 128 * (i + 1));
            CP_COMMIT();
        }

        // ---- S = Q K^T (2 products), nb-outer so exp interleaves ----
        uint32_t pfh[8][4], pfl[8][4];
        #pragma unroll
        for (int nb = 0; nb < 8; ++nb) {
            float s0[4] = {0.f, 0.f, 0.f, 0.f};
            float s1[4] = {0.f, 0.f, 0.f, 0.f};
            #pragma unroll
            for (int k16 = 0; k16 < 8; ++k16) {
                uint32_t fh[4];
                const uint32_t ad = (uint32_t)(k16 >> 1) * 8192 +
                    ((b_base + (uint32_t)nb * 1024u) ^ ((uint32_t)(k16 & 1) << 5));
                ldsm_x4(fh, curK + ad);
                mma16816h(s0, qfh[k16], fh);
                mma16816h(s1, qfh[k16], fh + 2);
                mma16816h(s0, qfl[k16], fh);
                mma16816h(s1, qfl[k16], fh + 2);
            }
            exp_pack4(s0, lsum0, lsum1, &pfh[nb][0], &pfl[nb][0]);
            exp_pack4(s1, lsum0, lsum1, &pfh[nb][2], &pfl[nb][2]);
        }

        // ---- y += P V (2 products) ----
        #pragma unroll
        for (int k16 = 0; k16 < 8; ++k16) {
            #pragma unroll
            for (int nb = 0; nb < 8; ++nb) {
                uint32_t fv[4];
                const uint32_t ad = (uint32_t)(k16 >> 1) * 8192 +
                    ((b_base + (uint32_t)nb * 1024u) ^ ((uint32_t)(k16 & 1) << 5));
                ldsm_x4(fv, curV + ad);
                mma16816h(yacc[2 * nb],     pfh[k16], fv);
                mma16816h(yacc[2 * nb + 1], pfh[k16], fv + 2);
                mma16816h(yacc[2 * nb],     pfl[k16], fv);
                mma16816h(yacc[2 * nb + 1], pfl[k16], fv + 2);
            }
        }
    }
#undef FA_LD1

    // ---- normalize + split + store ----
    lsum0 += __shfl_xor_sync(0xffffffffu, lsum0, 1);
    lsum0 += __shfl_xor_sync(0xffffffffu, lsum0, 2);
    lsum1 += __shfl_xor_sync(0xffffffffu, lsum1, 1);
    lsum1 += __shfl_xor_sync(0xffffffffu, lsum1, 2);
    const float inv0 = 1.0f / lsum0;
    const float inv1 = 1.0f / lsum1;

    const int q0 = bq + wid * 16 + (lane >> 2);
    const long long ob = (long long)b * SEQ * EMB + (long long)h * HDIM;
    #pragma unroll
    for (int T = 0; T < 16; ++T) {
        const int dcol = T * 8 + ((lane & 3) << 1);
        const float v0 = yacc[T][0] * inv0;
        const float v1 = yacc[T][1] * inv0;
        const float v2 = yacc[T][2] * inv1;
        const float v3 = yacc[T][3] * inv1;
        const __half h0 = __float2half_rn(v0);
        const __half h1 = __float2half_rn(v1);
        const __half h2 = __float2half_rn(v2);
        const __half h3 = __float2half_rn(v3);
        __half2 hh0, ll0, hh1, ll1;
        hh0.x = h0; hh0.y = h1;
        ll0.x = __float2half_rn(v0 - __half2float(h0));
        ll0.y = __float2half_rn(v1 - __half2float(h1));
        hh1.x = h2; hh1.y = h3;
        ll1.x = __float2half_rn(v2 - __half2float(h2));
        ll1.y = __float2half_rn(v3 - __half2float(h3));
        const long long o0 = ob + (long long)q0 * EMB + dcol;
        const long long o1 = o0 + 8LL * EMB;
        *(__half2*)(g_yh + o0) = hh0;
        *(__half2*)(g_yl + o0) = ll0;
        *(__half2*)(g_yh + o1) = hh1;
        *(__half2*)(g_yl + o1) = ll1;
    }
}

// ---------------------------------------------------------------------------
// fp32 -> (hi, lo) fp16 split, flat, 4 elems/thread
// ---------------------------------------------------------------------------
struct h4 { __half x, y, z, w; };

__global__ void __launch_bounds__(256) split_kernel(
    const float* __restrict__ s, __half* __restrict__ h,
    __half* __restrict__ l, int n4)
{
    const int i = blockIdx.x * 256 + threadIdx.x;
    if (i >= n4) return;
    const float4 v = ((const float4*)s)[i];
    h4 hh, lo;
    hh.x = __float2half_rn(v.x); lo.x = __float2half_rn(v.x - __half2float(hh.x));
    hh.y = __float2half_rn(v.y); lo.y = __float2half_rn(v.y - __half2float(hh.y));
    hh.z = __float2half_rn(v.z); lo.z = __float2half_rn(v.z - __half2float(hh.z));
    hh.w = __float2half_rn(v.w); lo.w = __float2half_rn(v.w - __half2float(hh.w));
    ((h4*)h)[i] = hh;
    ((h4*)l)[i] = lo;
}

// ---------------------------------------------------------------------------
// Transpose (hi only): src [K,N] fp32 row-major -> dst [N,K] fp16
// ---------------------------------------------------------------------------
__global__ void __launch_bounds__(256) tsplit_kernel(
    const float* __restrict__ s, __half* __restrict__ h, int K, int N)
{
    __shared__ float tile[32][33];
    const int tx = threadIdx.x, ty = threadIdx.y;
    const int n0 = blockIdx.x * 32, k0 = blockIdx.y * 32;
    #pragma unroll
    for (int j = 0; j < 32; j += 8)
        tile[ty + j][tx] = s[(long long)(k0 + ty + j) * N + n0 + tx];
    __syncthreads();
    #pragma unroll
    for (int j = 0; j < 32; j += 8) {
        const float v = tile[tx][ty + j];
        const long long o = (long long)(n0 + ty + j) * K + k0 + tx;
        h[o] = __float2half_rn(v);
    }
}

// ---------------------------------------------------------------------------
// Launch sequence
// ---------------------------------------------------------------------------
extern "C" void kernel_launch(void* const* d_in, const int* in_sizes, int n_in,
                              void* d_out, int out_size)
{
    const float* x      = (const float*)d_in[0];
    const int*   pos    = (const int*)  d_in[1];
    const float* W_attn = (const float*)d_in[2];
    const float* b_attn = (const float*)d_in[3];
    const float* W_proj = (const float*)d_in[4];
    const float* b_proj = (const float*)d_in[5];
    float* out = (float*)d_out;

    __half *xh, *xl, *wah, *yh, *yl, *wph;
    cudaGetSymbolAddress((void**)&xh,  g_xh);  cudaGetSymbolAddress((void**)&xl,  g_xl);
    cudaGetSymbolAddress((void**)&wah, g_wah);
    cudaGetSymbolAddress((void**)&yh,  g_yh);  cudaGetSymbolAddress((void**)&yl,  g_yl);
    cudaGetSymbolAddress((void**)&wph, g_wph);

    cudaFuncSetAttribute(gemm_f16,
                         cudaFuncAttributeMaxDynamicSharedMemorySize, GSMEM);
    cudaFuncSetAttribute(gemm_qkv,
                         cudaFuncAttributeMaxDynamicSharedMemorySize, GSMEM);
    cudaFuncSetAttribute(flash_kernel,
                         cudaFuncAttributeMaxDynamicSharedMemorySize, FA_SMEM);

    const dim3 tb(32, 8, 1);

    // 0. input conversions (fp16; x hi/lo, weights hi only)
    split_kernel<<<(BATCH * SEQ * EMB / 4 + 255) / 256, 256>>>(x, xh, xl,
                                                               BATCH * SEQ * EMB / 4);
    tsplit_kernel<<<dim3(E3 / 32, EMB / 32, 1), tb>>>(W_attn, wah, EMB, E3);
    tsplit_kernel<<<dim3(EMB / 32, EMB / 32, 1), tb>>>(W_proj, wph, EMB, EMB);

    // 1. qkv GEMM with fused bias + RoPE + hi/lo split + V transpose
    gemm_qkv<<<dim3(E3 / 128, (BATCH * SEQ) / 128, 1), 256, GSMEM>>>(
        xh, xl, wah, b_attn, pos);

    // 2. fused attention (2-product) -> yh/yl
    flash_kernel<<<dim3(SEQ / 128, BATCH * NH, 1), 256, FA_SMEM>>>();

    // 3. out = y @ W_proj + b (2-product): M=4096, N=2048, K=2048
    gemm_f16<<<dim3(EMB / 128, (BATCH * SEQ) / 128, 1), 256, GSMEM>>>(
        yh, yl, wph, out, b_proj, EMB, EMB, EMB, EMB);
}

// round 10
// speedup vs baseline: 1.1669x; 1.1652x over previous
#include <cuda_runtime.h>
#include <cuda_fp16.h>
#include <cstdint>
#include <math.h>

// Problem constants
#define BATCH 2
#define SEQ   2048
#define EMB   2048
#define NH    16
#define HDIM  128
#define E3    6144

#define SM_SCALE 0.08838834764831845f

// ---------------------------------------------------------------------------
// Scratch (__device__ globals; allocation-free rule)
// ---------------------------------------------------------------------------
__device__ __half g_xh[(size_t)BATCH * SEQ * EMB];
__device__ __half g_xl[(size_t)BATCH * SEQ * EMB];
__device__ __half g_wah[(size_t)E3 * EMB];                         // W_attn^T hi
__device__ __half g_qkh[(size_t)BATCH * SEQ * E3];                 // q hi | k hi
__device__ __half g_vth[(size_t)BATCH * NH * HDIM * SEQ];          // V^T hi
__device__ __half g_yh[(size_t)BATCH * SEQ * EMB];
__device__ __half g_yl[(size_t)BATCH * SEQ * EMB];
__device__ __half g_wph[(size_t)EMB * EMB];                        // W_proj^T hi
__device__ float  g_cos[(size_t)BATCH * SEQ * 64];                 // RoPE tables
__device__ float  g_sin[(size_t)BATCH * SEQ * 64];

// ---------------------------------------------------------------------------
// PTX helpers (arch-generic: cp.async, ldmatrix, mma.sync)
// ---------------------------------------------------------------------------
__device__ __forceinline__ uint32_t smem_u32(const void* p) {
    uint32_t a;
    asm("{ .reg .u64 t; cvta.to.shared.u64 t, %1; cvt.u32.u64 %0, t; }"
        : "=r"(a) : "l"(p));
    return a;
}
#define CP16(dst, src) \
    asm volatile("cp.async.cg.shared.global [%0], [%1], 16;" :: "r"(dst), "l"(src))
#define CP_COMMIT() asm volatile("cp.async.commit_group;" ::: "memory")
#define CP_WAIT0()  asm volatile("cp.async.wait_group 0;" ::: "memory")
#define CP_WAIT1()  asm volatile("cp.async.wait_group 1;" ::: "memory")
#define CP_WAIT2()  asm volatile("cp.async.wait_group 2;" ::: "memory")

__device__ __forceinline__ void ldsm_x4(uint32_t* r, uint32_t a) {
    asm volatile("ldmatrix.sync.aligned.m8n8.x4.shared.b16 {%0,%1,%2,%3}, [%4];"
        : "=r"(r[0]), "=r"(r[1]), "=r"(r[2]), "=r"(r[3]) : "r"(a));
}
__device__ __forceinline__ void mma16816h(float* d, const uint32_t* a,
                                          const uint32_t* b) {
    asm volatile(
        "mma.sync.aligned.m16n8k16.row.col.f32.f16.f16.f32 "
        "{%0,%1,%2,%3}, {%4,%5,%6,%7}, {%8,%9}, {%0,%1,%2,%3};"
        : "+f"(d[0]), "+f"(d[1]), "+f"(d[2]), "+f"(d[3])
        : "r"(a[0]), "r"(a[1]), "r"(a[2]), "r"(a[3]), "r"(b[0]), "r"(b[1]));
}

// SMEM sub-tile: 128 rows x 32 fp16 = 64B rows, XOR swizzle (no padding).
#define ROW_B  64
#define TILE_B 8192
#define STB    (3 * TILE_B)          // stage bytes (Ah, Al, Bh)
#define GSMEM  (3 * STB)             // 73728: 3 stages; also >= 128*129*4 staging

// ===========================================================================
// Shared GEMM mainloop (2 products: A*Bh with A=Ah+Al): computes acc[4][4][4]
// ===========================================================================
#define GEMM_MAINLOOP(Ah, Al, Bh, K, lda, ldb)                               \
    const int r0 = tid >> 2;                                                 \
    const int cc = tid & 3;                                                  \
    const uint32_t swsel = (uint32_t)((r0 & 3) ^ ((r0 >> 2) & 1));           \
    const uint32_t d0 = (uint32_t)r0 * ROW_B + ((cc ^ swsel) << 4);          \
    const uint32_t d1 = d0 + 64 * ROW_B;                                     \
    const __half* pAh0 = (Ah) + (bm + r0) * (long long)(lda) + cc * 8;       \
    const __half* pAh1 = pAh0 + 64LL * (lda);                                \
    const __half* pAl0 = (Al) + (bm + r0) * (long long)(lda) + cc * 8;       \
    const __half* pAl1 = pAl0 + 64LL * (lda);                                \
    const __half* pBh0 = (Bh) + (bn + r0) * (long long)(ldb) + cc * 8;       \
    const __half* pBh1 = pBh0 + 64LL * (ldb);                                \
    const int nt = (K) >> 5;                                                 \
    ISSUE_STAGE(sb);                                                         \
    CP_COMMIT();                                                             \
    ISSUE_STAGE(sb + STB);                                                   \
    CP_COMMIT();                                                             \
    float acc[4][4][4];                                                      \
    _Pragma("unroll")                                                        \
    for (int i = 0; i < 4; ++i)                                              \
        _Pragma("unroll")                                                    \
        for (int j = 0; j < 4; ++j)                                          \
            _Pragma("unroll")                                                \
            for (int k = 0; k < 4; ++k) acc[i][j][k] = 0.f;                  \
    const int row_a = wm * 64 + (lane & 15);                                 \
    const uint32_t sa = (uint32_t)((row_a & 3) ^ ((row_a >> 2) & 1));        \
    const uint32_t a_base =                                                  \
        (uint32_t)row_a * ROW_B + ((((uint32_t)lane >> 4) ^ sa) << 4);       \
    const int row_b = wn * 32 + ((lane >> 4) << 3) + (lane & 7);             \
    const uint32_t sbw = (uint32_t)((row_b & 3) ^ ((row_b >> 2) & 1));       \
    const uint32_t b_base =                                                  \
        (uint32_t)row_b * ROW_B + (((((uint32_t)lane >> 3) & 1) ^ sbw) << 4);\
    uint32_t cur_st = sb;                                                    \
    uint32_t iss_st = sb + 2 * STB;                                          \
    for (int t = 0; t < nt; ++t) {                                           \
        CP_WAIT1();                                                          \
        __syncthreads();                                                     \
        if (t + 2 < nt) ISSUE_STAGE(iss_st);                                 \
        CP_COMMIT();                                                         \
        const uint32_t pAh = cur_st, pAl = cur_st + TILE_B,                  \
                       pBh = cur_st + 2 * TILE_B;                            \
        _Pragma("unroll")                                                    \
        for (int k16 = 0; k16 < 2; ++k16) {                                  \
            const uint32_t kx = (uint32_t)(k16 << 5);                        \
            uint32_t fBh[2][4];                                              \
            _Pragma("unroll")                                                \
            for (int bt = 0; bt < 2; ++bt)                                   \
                ldsm_x4(fBh[bt], pBh + ((b_base + bt * (16 * ROW_B)) ^ kx)); \
            _Pragma("unroll")                                                \
            for (int mt = 0; mt < 4; ++mt) {                                 \
                uint32_t fAh[4], fAl[4];                                     \
                ldsm_x4(fAh, pAh + ((a_base + mt * (16 * ROW_B)) ^ kx));     \
                ldsm_x4(fAl, pAl + ((a_base + mt * (16 * ROW_B)) ^ kx));     \
                _Pragma("unroll")                                            \
                for (int n8 = 0; n8 < 4; ++n8) {                             \
                    const uint32_t* bh = &fBh[n8 >> 1][(n8 & 1) << 1];       \
                    mma16816h(acc[mt][n8], fAh, bh);                         \
                    mma16816h(acc[mt][n8], fAl, bh);                         \
                }                                                            \
            }                                                                \
        }                                                                    \
        uint32_t nxt = cur_st + STB;                                         \
        if (nxt >= sb + 3 * STB) nxt = sb;                                   \
        cur_st = nxt;                                                        \
        nxt = iss_st + STB;                                                  \
        if (nxt >= sb + 3 * STB) nxt = sb;                                   \
        iss_st = nxt;                                                        \
    }

#define ISSUE_STAGE(st)                                              \
    do {                                                             \
        CP16((st) + 0 * TILE_B + d0, pAh0);                          \
        CP16((st) + 0 * TILE_B + d1, pAh1);                          \
        CP16((st) + 1 * TILE_B + d0, pAl0);                          \
        CP16((st) + 1 * TILE_B + d1, pAl1);                          \
        CP16((st) + 2 * TILE_B + d0, pBh0);                          \
        CP16((st) + 2 * TILE_B + d1, pBh1);                          \
        pAh0 += 32; pAh1 += 32; pAl0 += 32; pAl1 += 32;              \
        pBh0 += 32; pBh1 += 32;                                      \
    } while (0)

// ---------------------------------------------------------------------------
// Generic NT fp16 GEMM (proj): C = A @ Bh + bias (fp32 out)
// ---------------------------------------------------------------------------
__global__ void __launch_bounds__(256, 2) gemm_f16(
    const __half* __restrict__ Ah, const __half* __restrict__ Al,
    const __half* __restrict__ Bh,
    float* __restrict__ C, const float* __restrict__ bias,
    int K, int lda, int ldb, int ldc)
{
    extern __shared__ char smem[];
    __shared__ float s_bias[128];

    const int tid  = threadIdx.x;
    const int wid  = tid >> 5, lane = tid & 31;
    const int wm   = wid & 1;
    const int wn   = wid >> 1;
    const long long bm = (long long)blockIdx.y * 128;
    const long long bn = (long long)blockIdx.x * 128;
    const uint32_t sb = smem_u32(smem);

    if (tid < 128) s_bias[tid] = bias[bn + tid];

    GEMM_MAINLOOP(Ah, Al, Bh, K, lda, ldb)

    #pragma unroll
    for (int mt = 0; mt < 4; ++mt) {
        const long long r = bm + wm * 64 + mt * 16 + (lane >> 2);
        float* row0 = C + r * ldc + bn + wn * 32;
        float* row1 = row0 + 8LL * ldc;
        #pragma unroll
        for (int n8 = 0; n8 < 4; ++n8) {
            const int c = n8 * 8 + ((lane & 3) << 1);
            const float b0 = s_bias[wn * 32 + c];
            const float b1 = s_bias[wn * 32 + c + 1];
            float2 v0, v1;
            v0.x = acc[mt][n8][0] + b0;
            v0.y = acc[mt][n8][1] + b1;
            v1.x = acc[mt][n8][2] + b0;
            v1.y = acc[mt][n8][3] + b1;
            *(float2*)(row0 + c) = v0;
            *(float2*)(row1 + c) = v1;
        }
    }
}

// ---------------------------------------------------------------------------
// QKV GEMM with fused RoPE (table-based) / V-transpose epilogue.
//   q/k (bn<4096):  RoPE via g_cos/g_sin, write fp16 hi to g_qkh
//   v (bn>=4096):   transpose, write fp16 hi to g_vth [(b,h),d,l]
// ---------------------------------------------------------------------------
__global__ void __launch_bounds__(256, 2) gemm_qkv(
    const __half* __restrict__ Ah, const __half* __restrict__ Al,
    const __half* __restrict__ Bh,
    const float* __restrict__ bias)
{
    extern __shared__ char smem[];
    __shared__ float s_bias[128];

    const int tid  = threadIdx.x;
    const int wid  = tid >> 5, lane = tid & 31;
    const int wm   = wid & 1;
    const int wn   = wid >> 1;
    const long long bm = (long long)blockIdx.y * 128;
    const long long bn = (long long)blockIdx.x * 128;
    const uint32_t sb = smem_u32(smem);

    if (tid < 128) s_bias[tid] = bias[bn + tid];

    GEMM_MAINLOOP(Ah, Al, Bh, EMB, EMB, EMB)

    // ---- stage biased fp32 tile into smem [128][129] ----
    __syncthreads();            // all warps done reading pipeline smem
    float* st = (float*)smem;
    #pragma unroll
    for (int mt = 0; mt < 4; ++mt) {
        const int rr = wm * 64 + mt * 16 + (lane >> 2);
        #pragma unroll
        for (int n8 = 0; n8 < 4; ++n8) {
            const int c = wn * 32 + n8 * 8 + ((lane & 3) << 1);
            const float b0 = s_bias[c], b1 = s_bias[c + 1];
            st[rr * 129 + c]           = acc[mt][n8][0] + b0;
            st[rr * 129 + c + 1]       = acc[mt][n8][1] + b1;
            st[(rr + 8) * 129 + c]     = acc[mt][n8][2] + b0;
            st[(rr + 8) * 129 + c + 1] = acc[mt][n8][3] + b1;
        }
    }
    __syncthreads();

    if (bn < 2 * EMB) {
        // ---- q or k head: RoPE via precomputed tables (hi only) ----
        #pragma unroll
        for (int it = 0; it < 32; ++it) {
            const int idx = it * 256 + tid;
            const int r = idx >> 6, j = idx & 63;
            const float v0 = st[r * 129 + j];
            const float v1 = st[r * 129 + j + 64];
            const long long tix = (bm + r) * 64 + j;
            const float cs = g_cos[tix];
            const float sn = g_sin[tix];
            const long long o = (bm + r) * (long long)E3 + bn;
            g_qkh[o + j]      = __float2half_rn(v0 * cs - v1 * sn);
            g_qkh[o + j + 64] = __float2half_rn(v1 * cs + v0 * sn);
        }
    } else {
        // ---- v head: transpose to [(b,h), d, l] ----
        const int hh = (int)((bn - 2 * EMB) >> 7);
        const int bb = (int)(bm >> 11);
        const int lbase = (int)(bm & (SEQ - 1));
        const long long vbase =
            ((long long)(bb * NH + hh) * HDIM) * SEQ + lbase;
        #pragma unroll
        for (int it = 0; it < 64; ++it) {
            const int idx = it * 256 + tid;
            const int d = idx >> 7, l = idx & 127;
            g_vth[vbase + (long long)d * SEQ + l] =
                __float2half_rn(st[l * 129 + d]);
        }
    }
}

// ---------------------------------------------------------------------------
// RoPE table prep: g_cos/g_sin[bl][j] = cos/sin(pos[bl] * 10000^(-j/64))
// ---------------------------------------------------------------------------
__global__ void __launch_bounds__(256) rope_prep_kernel(const int* __restrict__ pos)
{
    const int idx = blockIdx.x * 256 + threadIdx.x;   // BATCH*SEQ*64
    const int j  = idx & 63;
    const int bl = idx >> 6;
    const float p = (float)pos[bl];
    const float invf = expf(-(float)j * 0.14391156831212787f);
    float s, c;
    sincosf(p * invf, &s, &c);
    g_cos[idx] = c;
    g_sin[idx] = s;
}

// ---------------------------------------------------------------------------
// exp + pack 4 fp32 -> fp16 hi A-fragments, accumulate row sums
// ---------------------------------------------------------------------------
__device__ __forceinline__ void exp_pack4h(const float* s, float& lsum0,
                                           float& lsum1, uint32_t* ph)
{
    const float e0 = __expf(s[0] * SM_SCALE);
    const float e1 = __expf(s[1] * SM_SCALE);
    const float e2 = __expf(s[2] * SM_SCALE);
    const float e3 = __expf(s[3] * SM_SCALE);
    lsum0 += e0 + e1;
    lsum1 += e2 + e3;
    asm("cvt.rn.f16x2.f32 %0, %1, %2;" : "=r"(ph[0]) : "f"(e1), "f"(e0));
    asm("cvt.rn.f16x2.f32 %0, %1, %2;" : "=r"(ph[1]) : "f"(e3), "f"(e2));
}

// ---------------------------------------------------------------------------
// Fused flash attention, plain fp16 S and PV (Q hi, K hi, P hi, V hi).
// SMEM: Qh (32K) + K0|K1 (32K each) + V0|V1 (32K each) = 160 KB.
// ---------------------------------------------------------------------------
#define FA_SMEM (160 * 1024)

__global__ void __launch_bounds__(256) flash_kernel()
{
    extern __shared__ char smem[];
    const int z = blockIdx.y;
    const int b = z >> 4, h = z & 15;
    const int bq = blockIdx.x * 128;
    const int tid = threadIdx.x;
    const int wid = tid >> 5, lane = tid & 31;

    const uint32_t sb  = smem_u32(smem);
    const uint32_t BQh = sb;
    const uint32_t K0 = sb + 32768,  K1 = sb + 65536;
    const uint32_t V0 = sb + 98304,  V1 = sb + 131072;

    const int r0 = tid >> 2;
    const int cc = tid & 3;
    const uint32_t swsel = (uint32_t)((r0 & 3) ^ ((r0 >> 2) & 1));
    const uint32_t d0 = (uint32_t)r0 * 64 + ((cc ^ swsel) << 4);
    const uint32_t d1 = d0 + 64 * 64;

    const long long zq = (long long)b * SEQ * E3 + (long long)h * HDIM;
    const __half* Qh = g_qkh + zq;
    const __half* Kh = Qh + EMB;
    const __half* Vh = g_vth + (long long)z * HDIM * SEQ;

#define FA_LD1(buf, G, rowbase, ldx, colbase)                              \
    do { _Pragma("unroll")                                                 \
        for (int kc = 0; kc < 4; ++kc) {                                   \
            const long long off = ((long long)(rowbase) + r0) * (ldx)      \
                                  + (colbase) + kc * 32 + cc * 8;          \
            CP16((buf) + kc * 8192 + d0, (G) + off);                       \
            CP16((buf) + kc * 8192 + d1, (G) + off + 64LL * (ldx));        \
        }                                                                  \
    } while (0)

    // prologue: Q, K0, V0
    FA_LD1(BQh, Qh, bq, E3, 0);
    CP_COMMIT();
    FA_LD1(K0, Kh, 0, E3, 0);
    CP_COMMIT();
    FA_LD1(V0, Vh, 0, SEQ, 0);
    CP_COMMIT();

    CP_WAIT2();          // Q resident
    __syncthreads();

    const int row_a = wid * 16 + (lane & 15);
    const uint32_t swA = (uint32_t)((row_a & 3) ^ ((row_a >> 2) & 1));
    const uint32_t a_base =
        (uint32_t)row_a * 64 + ((((uint32_t)lane >> 4) ^ swA) << 4);
    uint32_t qfh[8][4];
    #pragma unroll
    for (int k16 = 0; k16 < 8; ++k16) {
        const uint32_t ad = (uint32_t)(k16 >> 1) * 8192 +
                            (a_base ^ ((uint32_t)(k16 & 1) << 5));
        ldsm_x4(qfh[k16], BQh + ad);
    }

    const int row_b = ((lane >> 4) << 3) + (lane & 7);
    const uint32_t swB = (uint32_t)((row_b & 3) ^ ((row_b >> 2) & 1));
    const uint32_t b_base =
        (uint32_t)row_b * 64 + (((((uint32_t)lane >> 3) & 1) ^ swB) << 4);

    float yacc[16][4];
    #pragma unroll
    for (int i = 0; i < 16; ++i)
        #pragma unroll
        for (int j = 0; j < 4; ++j) yacc[i][j] = 0.f;
    float lsum0 = 0.f, lsum1 = 0.f;

    for (int i = 0; i < 16; ++i) {
        const uint32_t curK = (i & 1) ? K1 : K0;
        const uint32_t curV = (i & 1) ? V1 : V0;

        CP_WAIT0();          // K_i, V_i resident
        __syncthreads();     // everyone done with buffers of iter i-1

        if (i < 15) {
            FA_LD1((i & 1) ? K0 : K1, Kh, 128 * (i + 1), E3, 0);
            CP_COMMIT();
            FA_LD1((i & 1) ? V0 : V1, Vh, 0, SEQ, 128 * (i + 1));
            CP_COMMIT();
        }

        // ---- S = Q K^T (fp16), nb-outer so exp interleaves ----
        uint32_t pfh[8][4];
        #pragma unroll
        for (int nb = 0; nb < 8; ++nb) {
            float s0[4] = {0.f, 0.f, 0.f, 0.f};
            float s1[4] = {0.f, 0.f, 0.f, 0.f};
            #pragma unroll
            for (int k16 = 0; k16 < 8; ++k16) {
                uint32_t fh[4];
                const uint32_t ad = (uint32_t)(k16 >> 1) * 8192 +
                    ((b_base + (uint32_t)nb * 1024u) ^ ((uint32_t)(k16 & 1) << 5));
                ldsm_x4(fh, curK + ad);
                mma16816h(s0, qfh[k16], fh);
                mma16816h(s1, qfh[k16], fh + 2);
            }
            exp_pack4h(s0, lsum0, lsum1, &pfh[nb][0]);
            exp_pack4h(s1, lsum0, lsum1, &pfh[nb][2]);
        }

        // ---- y += P V (fp16) ----
        #pragma unroll
        for (int k16 = 0; k16 < 8; ++k16) {
            #pragma unroll
            for (int nb = 0; nb < 8; ++nb) {
                uint32_t fv[4];
                const uint32_t ad = (uint32_t)(k16 >> 1) * 8192 +
                    ((b_base + (uint32_t)nb * 1024u) ^ ((uint32_t)(k16 & 1) << 5));
                ldsm_x4(fv, curV + ad);
                mma16816h(yacc[2 * nb],     pfh[k16], fv);
                mma16816h(yacc[2 * nb + 1], pfh[k16], fv + 2);
            }
        }
    }
#undef FA_LD1

    // ---- normalize + split + store ----
    lsum0 += __shfl_xor_sync(0xffffffffu, lsum0, 1);
    lsum0 += __shfl_xor_sync(0xffffffffu, lsum0, 2);
    lsum1 += __shfl_xor_sync(0xffffffffu, lsum1, 1);
    lsum1 += __shfl_xor_sync(0xffffffffu, lsum1, 2);
    const float inv0 = 1.0f / lsum0;
    const float inv1 = 1.0f / lsum1;

    const int q0 = bq + wid * 16 + (lane >> 2);
    const long long ob = (long long)b * SEQ * EMB + (long long)h * HDIM;
    #pragma unroll
    for (int T = 0; T < 16; ++T) {
        const int dcol = T * 8 + ((lane & 3) << 1);
        const float v0 = yacc[T][0] * inv0;
        const float v1 = yacc[T][1] * inv0;
        const float v2 = yacc[T][2] * inv1;
        const float v3 = yacc[T][3] * inv1;
        const __half h0 = __float2half_rn(v0);
        const __half h1 = __float2half_rn(v1);
        const __half h2 = __float2half_rn(v2);
        const __half h3 = __float2half_rn(v3);
        __half2 hh0, ll0, hh1, ll1;
        hh0.x = h0; hh0.y = h1;
        ll0.x = __float2half_rn(v0 - __half2float(h0));
        ll0.y = __float2half_rn(v1 - __half2float(h1));
        hh1.x = h2; hh1.y = h3;
        ll1.x = __float2half_rn(v2 - __half2float(h2));
        ll1.y = __float2half_rn(v3 - __half2float(h3));
        const long long o0 = ob + (long long)q0 * EMB + dcol;
        const long long o1 = o0 + 8LL * EMB;
        *(__half2*)(g_yh + o0) = hh0;
        *(__half2*)(g_yl + o0) = ll0;
        *(__half2*)(g_yh + o1) = hh1;
        *(__half2*)(g_yl + o1) = ll1;
    }
}

// ---------------------------------------------------------------------------
// fp32 -> (hi, lo) fp16 split, flat, 4 elems/thread
// ---------------------------------------------------------------------------
struct h4 { __half x, y, z, w; };

__global__ void __launch_bounds__(256) split_kernel(
    const float* __restrict__ s, __half* __restrict__ h,
    __half* __restrict__ l, int n4)
{
    const int i = blockIdx.x * 256 + threadIdx.x;
    if (i >= n4) return;
    const float4 v = ((const float4*)s)[i];
    h4 hh, lo;
    hh.x = __float2half_rn(v.x); lo.x = __float2half_rn(v.x - __half2float(hh.x));
    hh.y = __float2half_rn(v.y); lo.y = __float2half_rn(v.y - __half2float(hh.y));
    hh.z = __float2half_rn(v.z); lo.z = __float2half_rn(v.z - __half2float(hh.z));
    hh.w = __float2half_rn(v.w); lo.w = __float2half_rn(v.w - __half2float(hh.w));
    ((h4*)h)[i] = hh;
    ((h4*)l)[i] = lo;
}

// ---------------------------------------------------------------------------
// Transpose (hi only): src [K,N] fp32 row-major -> dst [N,K] fp16
// ---------------------------------------------------------------------------
__global__ void __launch_bounds__(256) tsplit_kernel(
    const float* __restrict__ s, __half* __restrict__ h, int K, int N)
{
    __shared__ float tile[32][33];
    const int tx = threadIdx.x, ty = threadIdx.y;
    const int n0 = blockIdx.x * 32, k0 = blockIdx.y * 32;
    #pragma unroll
    for (int j = 0; j < 32; j += 8)
        tile[ty + j][tx] = s[(long long)(k0 + ty + j) * N + n0 + tx];
    __syncthreads();
    #pragma unroll
    for (int j = 0; j < 32; j += 8) {
        const float v = tile[tx][ty + j];
        const long long o = (long long)(n0 + ty + j) * K + k0 + tx;
        h[o] = __float2half_rn(v);
    }
}

// ---------------------------------------------------------------------------
// Launch sequence
// ---------------------------------------------------------------------------
extern "C" void kernel_launch(void* const* d_in, const int* in_sizes, int n_in,
                              void* d_out, int out_size)
{
    const float* x      = (const float*)d_in[0];
    const int*   pos    = (const int*)  d_in[1];
    const float* W_attn = (const float*)d_in[2];
    const float* b_attn = (const float*)d_in[3];
    const float* W_proj = (const float*)d_in[4];
    const float* b_proj = (const float*)d_in[5];
    float* out = (float*)d_out;

    __half *xh, *xl, *wah, *yh, *yl, *wph;
    cudaGetSymbolAddress((void**)&xh,  g_xh);  cudaGetSymbolAddress((void**)&xl,  g_xl);
    cudaGetSymbolAddress((void**)&wah, g_wah);
    cudaGetSymbolAddress((void**)&yh,  g_yh);  cudaGetSymbolAddress((void**)&yl,  g_yl);
    cudaGetSymbolAddress((void**)&wph, g_wph);

    cudaFuncSetAttribute(gemm_f16,
                         cudaFuncAttributeMaxDynamicSharedMemorySize, GSMEM);
    cudaFuncSetAttribute(gemm_qkv,
                         cudaFuncAttributeMaxDynamicSharedMemorySize, GSMEM);
    cudaFuncSetAttribute(flash_kernel,
                         cudaFuncAttributeMaxDynamicSharedMemorySize, FA_SMEM);

    const dim3 tb(32, 8, 1);

    // 0. conversions + RoPE tables
    rope_prep_kernel<<<(BATCH * SEQ * 64) / 256, 256>>>(pos);
    split_kernel<<<(BATCH * SEQ * EMB / 4 + 255) / 256, 256>>>(x, xh, xl,
                                                               BATCH * SEQ * EMB / 4);
    tsplit_kernel<<<dim3(E3 / 32, EMB / 32, 1), tb>>>(W_attn, wah, EMB, E3);
    tsplit_kernel<<<dim3(EMB / 32, EMB / 32, 1), tb>>>(W_proj, wph, EMB, EMB);

    // 1. qkv GEMM with fused bias + table-RoPE + V transpose
    gemm_qkv<<<dim3(E3 / 128, (BATCH * SEQ) / 128, 1), 256, GSMEM>>>(
        xh, xl, wah, b_attn);

    // 2. fused attention (fp16) -> yh/yl
    flash_kernel<<<dim3(SEQ / 128, BATCH * NH, 1), 256, FA_SMEM>>>();

    // 3. out = y @ W_proj + b (2-product): M=4096, N=2048, K=2048
    gemm_f16<<<dim3(EMB / 128, (BATCH * SEQ) / 128, 1), 256, GSMEM>>>(
        yh, yl, wph, out, b_proj, EMB, EMB, EMB, EMB);
}

// round 11
// speedup vs baseline: 1.7049x; 1.4611x over previous
#include <cuda_runtime.h>
#include <cuda_fp16.h>
#include <cstdint>
#include <math.h>

// Problem constants
#define BATCH 2
#define SEQ   2048
#define EMB   2048
#define NH    16
#define HDIM  128
#define E3    6144

#define SM_SCALE 0.08838834764831845f

// ---------------------------------------------------------------------------
// Scratch (__device__ globals; allocation-free rule)
// ---------------------------------------------------------------------------
__device__ __half g_xh[(size_t)BATCH * SEQ * EMB];
__device__ __half g_wah[(size_t)E3 * EMB];                         // W_attn^T hi
__device__ __half g_qkh[(size_t)BATCH * SEQ * E3];                 // q hi | k hi
__device__ __half g_vth[(size_t)BATCH * NH * HDIM * SEQ];          // V^T hi
__device__ __half g_yh[(size_t)BATCH * SEQ * EMB];
__device__ __half g_wph[(size_t)EMB * EMB];                        // W_proj^T hi
__device__ float  g_cos[(size_t)BATCH * SEQ * 64];                 // RoPE tables
__device__ float  g_sin[(size_t)BATCH * SEQ * 64];

// ---------------------------------------------------------------------------
// PTX helpers (arch-generic: cp.async, ldmatrix, mma.sync)
// ---------------------------------------------------------------------------
__device__ __forceinline__ uint32_t smem_u32(const void* p) {
    uint32_t a;
    asm("{ .reg .u64 t; cvta.to.shared.u64 t, %1; cvt.u32.u64 %0, t; }"
        : "=r"(a) : "l"(p));
    return a;
}
#define CP16(dst, src) \
    asm volatile("cp.async.cg.shared.global [%0], [%1], 16;" :: "r"(dst), "l"(src))
#define CP_COMMIT() asm volatile("cp.async.commit_group;" ::: "memory")
#define CP_WAIT0()  asm volatile("cp.async.wait_group 0;" ::: "memory")
#define CP_WAIT1()  asm volatile("cp.async.wait_group 1;" ::: "memory")
#define CP_WAIT2()  asm volatile("cp.async.wait_group 2;" ::: "memory")

__device__ __forceinline__ void ldsm_x4(uint32_t* r, uint32_t a) {
    asm volatile("ldmatrix.sync.aligned.m8n8.x4.shared.b16 {%0,%1,%2,%3}, [%4];"
        : "=r"(r[0]), "=r"(r[1]), "=r"(r[2]), "=r"(r[3]) : "r"(a));
}
__device__ __forceinline__ void mma16816h(float* d, const uint32_t* a,
                                          const uint32_t* b) {
    asm volatile(
        "mma.sync.aligned.m16n8k16.row.col.f32.f16.f16.f32 "
        "{%0,%1,%2,%3}, {%4,%5,%6,%7}, {%8,%9}, {%0,%1,%2,%3};"
        : "+f"(d[0]), "+f"(d[1]), "+f"(d[2]), "+f"(d[3])
        : "r"(a[0]), "r"(a[1]), "r"(a[2]), "r"(a[3]), "r"(b[0]), "r"(b[1]));
}

// SMEM sub-tile: 128 rows x 32 fp16 = 64B rows, XOR swizzle (no padding).
#define ROW_B  64
#define TILE_B 8192
#define STB    (2 * TILE_B)          // stage bytes (Ah, Bh)
#define GSMEM  73728                 // >= 3*STB and >= 128*129*4 epilogue staging

// ===========================================================================
// Shared GEMM mainloop (single product Ah*Bh): computes acc[4][4][4]
// ===========================================================================
#define GEMM_MAINLOOP(Ah, Bh, K, lda, ldb)                                   \
    const int r0 = tid >> 2;                                                 \
    const int cc = tid & 3;                                                  \
    const uint32_t swsel = (uint32_t)((r0 & 3) ^ ((r0 >> 2) & 1));           \
    const uint32_t d0 = (uint32_t)r0 * ROW_B + ((cc ^ swsel) << 4);          \
    const uint32_t d1 = d0 + 64 * ROW_B;                                     \
    const __half* pAh0 = (Ah) + (bm + r0) * (long long)(lda) + cc * 8;       \
    const __half* pAh1 = pAh0 + 64LL * (lda);                                \
    const __half* pBh0 = (Bh) + (bn + r0) * (long long)(ldb) + cc * 8;       \
    const __half* pBh1 = pBh0 + 64LL * (ldb);                                \
    const int nt = (K) >> 5;                                                 \
    ISSUE_STAGE(sb);                                                         \
    CP_COMMIT();                                                             \
    ISSUE_STAGE(sb + STB);                                                   \
    CP_COMMIT();                                                             \
    float acc[4][4][4];                                                      \
    _Pragma("unroll")                                                        \
    for (int i = 0; i < 4; ++i)                                              \
        _Pragma("unroll")                                                    \
        for (int j = 0; j < 4; ++j)                                          \
            _Pragma("unroll")                                                \
            for (int k = 0; k < 4; ++k) acc[i][j][k] = 0.f;                  \
    const int row_a = wm * 64 + (lane & 15);                                 \
    const uint32_t sa = (uint32_t)((row_a & 3) ^ ((row_a >> 2) & 1));        \
    const uint32_t a_base =                                                  \
        (uint32_t)row_a * ROW_B + ((((uint32_t)lane >> 4) ^ sa) << 4);       \
    const int row_b = wn * 32 + ((lane >> 4) << 3) + (lane & 7);             \
    const uint32_t sbw = (uint32_t)((row_b & 3) ^ ((row_b >> 2) & 1));       \
    const uint32_t b_base =                                                  \
        (uint32_t)row_b * ROW_B + (((((uint32_t)lane >> 3) & 1) ^ sbw) << 4);\
    uint32_t cur_st = sb;                                                    \
    uint32_t iss_st = sb + 2 * STB;                                          \
    for (int t = 0; t < nt; ++t) {                                           \
        CP_WAIT1();                                                          \
        __syncthreads();                                                     \
        if (t + 2 < nt) ISSUE_STAGE(iss_st);                                 \
        CP_COMMIT();                                                         \
        const uint32_t pAh = cur_st, pBh = cur_st + TILE_B;                  \
        _Pragma("unroll")                                                    \
        for (int k16 = 0; k16 < 2; ++k16) {                                  \
            const uint32_t kx = (uint32_t)(k16 << 5);                        \
            uint32_t fBh[2][4];                                              \
            _Pragma("unroll")                                                \
            for (int bt = 0; bt < 2; ++bt)                                   \
                ldsm_x4(fBh[bt], pBh + ((b_base + bt * (16 * ROW_B)) ^ kx)); \
            _Pragma("unroll")                                                \
            for (int mt = 0; mt < 4; ++mt) {                                 \
                uint32_t fAh[4];                                             \
                ldsm_x4(fAh, pAh + ((a_base + mt * (16 * ROW_B)) ^ kx));     \
                _Pragma("unroll")                                            \
                for (int n8 = 0; n8 < 4; ++n8) {                             \
                    const uint32_t* bh = &fBh[n8 >> 1][(n8 & 1) << 1];       \
                    mma16816h(acc[mt][n8], fAh, bh);                         \
                }                                                            \
            }                                                                \
        }                                                                    \
        uint32_t nxt = cur_st + STB;                                         \
        if (nxt >= sb + 3 * STB) nxt = sb;                                   \
        cur_st = nxt;                                                        \
        nxt = iss_st + STB;                                                  \
        if (nxt >= sb + 3 * STB) nxt = sb;                                   \
        iss_st = nxt;                                                        \
    }

#define ISSUE_STAGE(st)                                              \
    do {                                                             \
        CP16((st) + 0 * TILE_B + d0, pAh0);                          \
        CP16((st) + 0 * TILE_B + d1, pAh1);                          \
        CP16((st) + 1 * TILE_B + d0, pBh0);                          \
        CP16((st) + 1 * TILE_B + d1, pBh1);                          \
        pAh0 += 32; pAh1 += 32;                                      \
        pBh0 += 32; pBh1 += 32;                                      \
    } while (0)

// ---------------------------------------------------------------------------
// Generic NT fp16 GEMM (proj): C = Ah @ Bh + bias (fp32 out)
// ---------------------------------------------------------------------------
__global__ void __launch_bounds__(256, 2) gemm_f16(
    const __half* __restrict__ Ah, const __half* __restrict__ Bh,
    float* __restrict__ C, const float* __restrict__ bias,
    int K, int lda, int ldb, int ldc)
{
    extern __shared__ char smem[];
    __shared__ float s_bias[128];

    const int tid  = threadIdx.x;
    const int wid  = tid >> 5, lane = tid & 31;
    const int wm   = wid & 1;
    const int wn   = wid >> 1;
    const long long bm = (long long)blockIdx.y * 128;
    const long long bn = (long long)blockIdx.x * 128;
    const uint32_t sb = smem_u32(smem);

    if (tid < 128) s_bias[tid] = bias[bn + tid];

    GEMM_MAINLOOP(Ah, Bh, K, lda, ldb)

    #pragma unroll
    for (int mt = 0; mt < 4; ++mt) {
        const long long r = bm + wm * 64 + mt * 16 + (lane >> 2);
        float* row0 = C + r * ldc + bn + wn * 32;
        float* row1 = row0 + 8LL * ldc;
        #pragma unroll
        for (int n8 = 0; n8 < 4; ++n8) {
            const int c = n8 * 8 + ((lane & 3) << 1);
            const float b0 = s_bias[wn * 32 + c];
            const float b1 = s_bias[wn * 32 + c + 1];
            float2 v0, v1;
            v0.x = acc[mt][n8][0] + b0;
            v0.y = acc[mt][n8][1] + b1;
            v1.x = acc[mt][n8][2] + b0;
            v1.y = acc[mt][n8][3] + b1;
            *(float2*)(row0 + c) = v0;
            *(float2*)(row1 + c) = v1;
        }
    }
}

// ---------------------------------------------------------------------------
// QKV GEMM with fused RoPE (table-based) / V-transpose epilogue.
//   q/k (bn<4096):  RoPE via g_cos/g_sin, write fp16 hi to g_qkh
//   v (bn>=4096):   transpose, write fp16 hi to g_vth [(b,h),d,l]
// ---------------------------------------------------------------------------
__global__ void __launch_bounds__(256, 2) gemm_qkv(
    const __half* __restrict__ Ah, const __half* __restrict__ Bh,
    const float* __restrict__ bias)
{
    extern __shared__ char smem[];
    __shared__ float s_bias[128];

    const int tid  = threadIdx.x;
    const int wid  = tid >> 5, lane = tid & 31;
    const int wm   = wid & 1;
    const int wn   = wid >> 1;
    const long long bm = (long long)blockIdx.y * 128;
    const long long bn = (long long)blockIdx.x * 128;
    const uint32_t sb = smem_u32(smem);

    if (tid < 128) s_bias[tid] = bias[bn + tid];

    GEMM_MAINLOOP(Ah, Bh, EMB, EMB, EMB)

    // ---- stage biased fp32 tile into smem [128][129] ----
    __syncthreads();            // all warps done reading pipeline smem
    float* st = (float*)smem;
    #pragma unroll
    for (int mt = 0; mt < 4; ++mt) {
        const int rr = wm * 64 + mt * 16 + (lane >> 2);
        #pragma unroll
        for (int n8 = 0; n8 < 4; ++n8) {
            const int c = wn * 32 + n8 * 8 + ((lane & 3) << 1);
            const float b0 = s_bias[c], b1 = s_bias[c + 1];
            st[rr * 129 + c]           = acc[mt][n8][0] + b0;
            st[rr * 129 + c + 1]       = acc[mt][n8][1] + b1;
            st[(rr + 8) * 129 + c]     = acc[mt][n8][2] + b0;
            st[(rr + 8) * 129 + c + 1] = acc[mt][n8][3] + b1;
        }
    }
    __syncthreads();

    if (bn < 2 * EMB) {
        // ---- q or k head: RoPE via precomputed tables (hi only) ----
        #pragma unroll
        for (int it = 0; it < 32; ++it) {
            const int idx = it * 256 + tid;
            const int r = idx >> 6, j = idx & 63;
            const float v0 = st[r * 129 + j];
            const float v1 = st[r * 129 + j + 64];
            const long long tix = (bm + r) * 64 + j;
            const float cs = g_cos[tix];
            const float sn = g_sin[tix];
            const long long o = (bm + r) * (long long)E3 + bn;
            g_qkh[o + j]      = __float2half_rn(v0 * cs - v1 * sn);
            g_qkh[o + j + 64] = __float2half_rn(v1 * cs + v0 * sn);
        }
    } else {
        // ---- v head: transpose to [(b,h), d, l] ----
        const int hh = (int)((bn - 2 * EMB) >> 7);
        const int bb = (int)(bm >> 11);
        const int lbase = (int)(bm & (SEQ - 1));
        const long long vbase =
            ((long long)(bb * NH + hh) * HDIM) * SEQ + lbase;
        #pragma unroll
        for (int it = 0; it < 64; ++it) {
            const int idx = it * 256 + tid;
            const int d = idx >> 7, l = idx & 127;
            g_vth[vbase + (long long)d * SEQ + l] =
                __float2half_rn(st[l * 129 + d]);
        }
    }
}

// ---------------------------------------------------------------------------
// RoPE table prep: g_cos/g_sin[bl][j] = cos/sin(pos[bl] * 10000^(-j/64))
// ---------------------------------------------------------------------------
__global__ void __launch_bounds__(256) rope_prep_kernel(const int* __restrict__ pos)
{
    const int idx = blockIdx.x * 256 + threadIdx.x;   // BATCH*SEQ*64
    const int j  = idx & 63;
    const int bl = idx >> 6;
    const float p = (float)pos[bl];
    const float invf = expf(-(float)j * 0.14391156831212787f);
    float s, c;
    sincosf(p * invf, &s, &c);
    g_cos[idx] = c;
    g_sin[idx] = s;
}

// ---------------------------------------------------------------------------
// exp + pack 4 fp32 -> fp16 hi A-fragments, accumulate row sums
// ---------------------------------------------------------------------------
__device__ __forceinline__ void exp_pack4h(const float* s, float& lsum0,
                                           float& lsum1, uint32_t* ph)
{
    const float e0 = __expf(s[0] * SM_SCALE);
    const float e1 = __expf(s[1] * SM_SCALE);
    const float e2 = __expf(s[2] * SM_SCALE);
    const float e3 = __expf(s[3] * SM_SCALE);
    lsum0 += e0 + e1;
    lsum1 += e2 + e3;
    asm("cvt.rn.f16x2.f32 %0, %1, %2;" : "=r"(ph[0]) : "f"(e1), "f"(e0));
    asm("cvt.rn.f16x2.f32 %0, %1, %2;" : "=r"(ph[1]) : "f"(e3), "f"(e2));
}

// ---------------------------------------------------------------------------
// Fused flash attention, plain fp16 S and PV (Q hi, K hi, P hi, V hi).
// SMEM: Qh (32K) + K0|K1 (32K each) + V0|V1 (32K each) = 160 KB.
// ---------------------------------------------------------------------------
#define FA_SMEM (160 * 1024)

__global__ void __launch_bounds__(256) flash_kernel()
{
    extern __shared__ char smem[];
    const int z = blockIdx.y;
    const int b = z >> 4, h = z & 15;
    const int bq = blockIdx.x * 128;
    const int tid = threadIdx.x;
    const int wid = tid >> 5, lane = tid & 31;

    const uint32_t sb  = smem_u32(smem);
    const uint32_t BQh = sb;
    const uint32_t K0 = sb + 32768,  K1 = sb + 65536;
    const uint32_t V0 = sb + 98304,  V1 = sb + 131072;

    const int r0 = tid >> 2;
    const int cc = tid & 3;
    const uint32_t swsel = (uint32_t)((r0 & 3) ^ ((r0 >> 2) & 1));
    const uint32_t d0 = (uint32_t)r0 * 64 + ((cc ^ swsel) << 4);
    const uint32_t d1 = d0 + 64 * 64;

    const long long zq = (long long)b * SEQ * E3 + (long long)h * HDIM;
    const __half* Qh = g_qkh + zq;
    const __half* Kh = Qh + EMB;
    const __half* Vh = g_vth + (long long)z * HDIM * SEQ;

#define FA_LD1(buf, G, rowbase, ldx, colbase)                              \
    do { _Pragma("unroll")                                                 \
        for (int kc = 0; kc < 4; ++kc) {                                   \
            const long long off = ((long long)(rowbase) + r0) * (ldx)      \
                                  + (colbase) + kc * 32 + cc * 8;          \
            CP16((buf) + kc * 8192 + d0, (G) + off);                       \
            CP16((buf) + kc * 8192 + d1, (G) + off + 64LL * (ldx));        \
        }                                                                  \
    } while (0)

    // prologue: Q, K0, V0
    FA_LD1(BQh, Qh, bq, E3, 0);
    CP_COMMIT();
    FA_LD1(K0, Kh, 0, E3, 0);
    CP_COMMIT();
    FA_LD1(V0, Vh, 0, SEQ, 0);
    CP_COMMIT();

    CP_WAIT2();          // Q resident
    __syncthreads();

    const int row_a = wid * 16 + (lane & 15);
    const uint32_t swA = (uint32_t)((row_a & 3) ^ ((row_a >> 2) & 1));
    const uint32_t a_base =
        (uint32_t)row_a * 64 + ((((uint32_t)lane >> 4) ^ swA) << 4);
    uint32_t qfh[8][4];
    #pragma unroll
    for (int k16 = 0; k16 < 8; ++k16) {
        const uint32_t ad = (uint32_t)(k16 >> 1) * 8192 +
                            (a_base ^ ((uint32_t)(k16 & 1) << 5));
        ldsm_x4(qfh[k16], BQh + ad);
    }

    const int row_b = ((lane >> 4) << 3) + (lane & 7);
    const uint32_t swB = (uint32_t)((row_b & 3) ^ ((row_b >> 2) & 1));
    const uint32_t b_base =
        (uint32_t)row_b * 64 + (((((uint32_t)lane >> 3) & 1) ^ swB) << 4);

    float yacc[16][4];
    #pragma unroll
    for (int i = 0; i < 16; ++i)
        #pragma unroll
        for (int j = 0; j < 4; ++j) yacc[i][j] = 0.f;
    float lsum0 = 0.f, lsum1 = 0.f;

    for (int i = 0; i < 16; ++i) {
        const uint32_t curK = (i & 1) ? K1 : K0;
        const uint32_t curV = (i & 1) ? V1 : V0;

        CP_WAIT0();          // K_i, V_i resident
        __syncthreads();     // everyone done with buffers of iter i-1

        if (i < 15) {
            FA_LD1((i & 1) ? K0 : K1, Kh, 128 * (i + 1), E3, 0);
            CP_COMMIT();
            FA_LD1((i & 1) ? V0 : V1, Vh, 0, SEQ, 128 * (i + 1));
            CP_COMMIT();
        }

        // ---- S = Q K^T (fp16), nb-outer so exp interleaves ----
        uint32_t pfh[8][4];
        #pragma unroll
        for (int nb = 0; nb < 8; ++nb) {
            float s0[4] = {0.f, 0.f, 0.f, 0.f};
            float s1[4] = {0.f, 0.f, 0.f, 0.f};
            #pragma unroll
            for (int k16 = 0; k16 < 8; ++k16) {
                uint32_t fh[4];
                const uint32_t ad = (uint32_t)(k16 >> 1) * 8192 +
                    ((b_base + (uint32_t)nb * 1024u) ^ ((uint32_t)(k16 & 1) << 5));
                ldsm_x4(fh, curK + ad);
                mma16816h(s0, qfh[k16], fh);
                mma16816h(s1, qfh[k16], fh + 2);
            }
            exp_pack4h(s0, lsum0, lsum1, &pfh[nb][0]);
            exp_pack4h(s1, lsum0, lsum1, &pfh[nb][2]);
        }

        // ---- y += P V (fp16) ----
        #pragma unroll
        for (int k16 = 0; k16 < 8; ++k16) {
            #pragma unroll
            for (int nb = 0; nb < 8; ++nb) {
                uint32_t fv[4];
                const uint32_t ad = (uint32_t)(k16 >> 1) * 8192 +
                    ((b_base + (uint32_t)nb * 1024u) ^ ((uint32_t)(k16 & 1) << 5));
                ldsm_x4(fv, curV + ad);
                mma16816h(yacc[2 * nb],     pfh[k16], fv);
                mma16816h(yacc[2 * nb + 1], pfh[k16], fv + 2);
            }
        }
    }
#undef FA_LD1

    // ---- normalize + store (hi only) ----
    lsum0 += __shfl_xor_sync(0xffffffffu, lsum0, 1);
    lsum0 += __shfl_xor_sync(0xffffffffu, lsum0, 2);
    lsum1 += __shfl_xor_sync(0xffffffffu, lsum1, 1);
    lsum1 += __shfl_xor_sync(0xffffffffu, lsum1, 2);
    const float inv0 = 1.0f / lsum0;
    const float inv1 = 1.0f / lsum1;

    const int q0 = bq + wid * 16 + (lane >> 2);
    const long long ob = (long long)b * SEQ * EMB + (long long)h * HDIM;
    #pragma unroll
    for (int T = 0; T < 16; ++T) {
        const int dcol = T * 8 + ((lane & 3) << 1);
        __half2 hh0, hh1;
        hh0.x = __float2half_rn(yacc[T][0] * inv0);
        hh0.y = __float2half_rn(yacc[T][1] * inv0);
        hh1.x = __float2half_rn(yacc[T][2] * inv1);
        hh1.y = __float2half_rn(yacc[T][3] * inv1);
        const long long o0 = ob + (long long)q0 * EMB + dcol;
        const long long o1 = o0 + 8LL * EMB;
        *(__half2*)(g_yh + o0) = hh0;
        *(__half2*)(g_yh + o1) = hh1;
    }
}

// ---------------------------------------------------------------------------
// fp32 -> fp16 convert, flat, 4 elems/thread
// ---------------------------------------------------------------------------
struct h4 { __half x, y, z, w; };

__global__ void __launch_bounds__(256) conv_kernel(
    const float* __restrict__ s, __half* __restrict__ h, int n4)
{
    const int i = blockIdx.x * 256 + threadIdx.x;
    if (i >= n4) return;
    const float4 v = ((const float4*)s)[i];
    h4 hh;
    hh.x = __float2half_rn(v.x);
    hh.y = __float2half_rn(v.y);
    hh.z = __float2half_rn(v.z);
    hh.w = __float2half_rn(v.w);
    ((h4*)h)[i] = hh;
}

// ---------------------------------------------------------------------------
// Transpose (hi only): src [K,N] fp32 row-major -> dst [N,K] fp16
// ---------------------------------------------------------------------------
__global__ void __launch_bounds__(256) tsplit_kernel(
    const float* __restrict__ s, __half* __restrict__ h, int K, int N)
{
    __shared__ float tile[32][33];
    const int tx = threadIdx.x, ty = threadIdx.y;
    const int n0 = blockIdx.x * 32, k0 = blockIdx.y * 32;
    #pragma unroll
    for (int j = 0; j < 32; j += 8)
        tile[ty + j][tx] = s[(long long)(k0 + ty + j) * N + n0 + tx];
    __syncthreads();
    #pragma unroll
    for (int j = 0; j < 32; j += 8) {
        const float v = tile[tx][ty + j];
        const long long o = (long long)(n0 + ty + j) * K + k0 + tx;
        h[o] = __float2half_rn(v);
    }
}

// ---------------------------------------------------------------------------
// Launch sequence
// ---------------------------------------------------------------------------
extern "C" void kernel_launch(void* const* d_in, const int* in_sizes, int n_in,
                              void* d_out, int out_size)
{
    const float* x      = (const float*)d_in[0];
    const int*   pos    = (const int*)  d_in[1];
    const float* W_attn = (const float*)d_in[2];
    const float* b_attn = (const float*)d_in[3];
    const float* W_proj = (const float*)d_in[4];
    const float* b_proj = (const float*)d_in[5];
    float* out = (float*)d_out;

    __half *xh, *wah, *yh, *wph;
    cudaGetSymbolAddress((void**)&xh,  g_xh);
    cudaGetSymbolAddress((void**)&wah, g_wah);
    cudaGetSymbolAddress((void**)&yh,  g_yh);
    cudaGetSymbolAddress((void**)&wph, g_wph);

    cudaFuncSetAttribute(gemm_f16,
                         cudaFuncAttributeMaxDynamicSharedMemorySize, GSMEM);
    cudaFuncSetAttribute(gemm_qkv,
                         cudaFuncAttributeMaxDynamicSharedMemorySize, GSMEM);
    cudaFuncSetAttribute(flash_kernel,
                         cudaFuncAttributeMaxDynamicSharedMemorySize, FA_SMEM);

    const dim3 tb(32, 8, 1);

    // 0. conversions + RoPE tables
    rope_prep_kernel<<<(BATCH * SEQ * 64) / 256, 256>>>(pos);
    conv_kernel<<<(BATCH * SEQ * EMB / 4 + 255) / 256, 256>>>(x, xh,
                                                              BATCH * SEQ * EMB / 4);
    tsplit_kernel<<<dim3(E3 / 32, EMB / 32, 1), tb>>>(W_attn, wah, EMB, E3);
    tsplit_kernel<<<dim3(EMB / 32, EMB / 32, 1), tb>>>(W_proj, wph, EMB, EMB);

    // 1. qkv GEMM (single product) with fused bias + table-RoPE + V transpose
    gemm_qkv<<<dim3(E3 / 128, (BATCH * SEQ) / 128, 1), 256, GSMEM>>>(
        xh, wah, b_attn);

    // 2. fused attention (fp16) -> yh
    flash_kernel<<<dim3(SEQ / 128, BATCH * NH, 1), 256, FA_SMEM>>>();

    // 3. out = y @ W_proj + b (single product): M=4096, N=2048, K=2048
    gemm_f16<<<dim3(EMB / 128, (BATCH * SEQ) / 128, 1), 256, GSMEM>>>(
        yh, wph, out, b_proj, EMB, EMB, EMB, EMB);
}

// round 13
// speedup vs baseline: 1.7697x; 1.0380x over previous
#include <cuda_runtime.h>
#include <cuda_fp16.h>
#include <cstdint>
#include <math.h>

// Problem constants
#define BATCH 2
#define SEQ   2048
#define EMB   2048
#define NH    16
#define HDIM  128
#define E3    6144

#define SM_SCALE 0.08838834764831845f

// ---------------------------------------------------------------------------
// Scratch (__device__ globals; allocation-free rule)
// ---------------------------------------------------------------------------
__device__ __half g_xh[(size_t)BATCH * SEQ * EMB];
__device__ __half g_wah[(size_t)E3 * EMB];                         // W_attn^T hi
__device__ __half g_qkh[(size_t)BATCH * SEQ * E3];                 // q hi | k hi
__device__ __half g_vth[(size_t)BATCH * NH * HDIM * SEQ];          // V^T hi
__device__ __half g_yh[(size_t)BATCH * SEQ * EMB];
__device__ __half g_wph[(size_t)EMB * EMB];                        // W_proj^T hi
__device__ float  g_cos[(size_t)BATCH * SEQ * 64];                 // RoPE tables
__device__ float  g_sin[(size_t)BATCH * SEQ * 64];

// ---------------------------------------------------------------------------
// PTX helpers (arch-generic: cp.async, ldmatrix, mma.sync)
// ---------------------------------------------------------------------------
__device__ __forceinline__ uint32_t smem_u32(const void* p) {
    uint32_t a;
    asm("{ .reg .u64 t; cvta.to.shared.u64 t, %1; cvt.u32.u64 %0, t; }"
        : "=r"(a) : "l"(p));
    return a;
}
#define CP16(dst, src) \
    asm volatile("cp.async.cg.shared.global [%0], [%1], 16;" :: "r"(dst), "l"(src))
#define CP_COMMIT() asm volatile("cp.async.commit_group;" ::: "memory")
#define CP_WAIT0()  asm volatile("cp.async.wait_group 0;" ::: "memory")
#define CP_WAIT1()  asm volatile("cp.async.wait_group 1;" ::: "memory")
#define CP_WAIT2()  asm volatile("cp.async.wait_group 2;" ::: "memory")

__device__ __forceinline__ void ldsm_x4(uint32_t* r, uint32_t a) {
    asm volatile("ldmatrix.sync.aligned.m8n8.x4.shared.b16 {%0,%1,%2,%3}, [%4];"
        : "=r"(r[0]), "=r"(r[1]), "=r"(r[2]), "=r"(r[3]) : "r"(a));
}
__device__ __forceinline__ void mma16816h(float* d, const uint32_t* a,
                                          const uint32_t* b) {
    asm volatile(
        "mma.sync.aligned.m16n8k16.row.col.f32.f16.f16.f32 "
        "{%0,%1,%2,%3}, {%4,%5,%6,%7}, {%8,%9}, {%0,%1,%2,%3};"
        : "+f"(d[0]), "+f"(d[1]), "+f"(d[2]), "+f"(d[3])
        : "r"(a[0]), "r"(a[1]), "r"(a[2]), "r"(a[3]), "r"(b[0]), "r"(b[1]));
}

// ---------------------------------------------------------------------------
// GEMM tile geometry (BK=64): 128 rows x 64 fp16 = 128B rows.
// Swizzle: chunk' = chunk ^ (row & 7)  (chunk = 16B group 0..7 within row).
//   - bank = f(chunk') only (row*128 ≡ 0 mod 128B); 8-lane ldsm phases hit
//     8 consecutive rows -> distinct chunk' -> conflict-free.
//   - row steps +8/+16/+32 preserve row&7 -> base offsets add linearly.
//   - chunk = (2*k16)|c (disjoint bits) -> k16 step == addr ^ (k16<<5).
// ---------------------------------------------------------------------------
#define GROW_B  128
#define GTILE_B 16384
#define STB     (2 * GTILE_B)        // stage bytes (Ah, Bh) = 32 KB
#define GSMEM   (3 * STB)            // 96 KB; also >= 128*129*4 epilogue staging

// ===========================================================================
// Shared GEMM mainloop (single product Ah*Bh, BK=64): computes acc[4][4][4]
// NOTE: ISSUE_STAGE references ldaL/ldbL/pA/pB/ldst, which are locals bound
// here (macro hygiene: GEMM_MAINLOOP params are NOT visible inside
// ISSUE_STAGE's own expansion, so bind them to real variables first).
// ===========================================================================
#define GEMM_MAINLOOP(Ah, Bh, K, lda, ldb)                                   \
    const long long ldaL = (lda), ldbL = (ldb);                              \
    const int lr0 = tid >> 3;            /* loader row 0..31 */              \
    const int lc  = tid & 7;             /* loader chunk 0..7 */             \
    const uint32_t ldst =                                                    \
        (uint32_t)lr0 * GROW_B + (((uint32_t)lc ^ (lr0 & 7)) << 4);          \
    const __half* pA = (Ah) + (bm + lr0) * ldaL + lc * 8;                    \
    const __half* pB = (Bh) + (bn + lr0) * ldbL + lc * 8;                    \
    const int nt = (K) >> 6;                                                 \
    ISSUE_STAGE(sb);                                                         \
    CP_COMMIT();                                                             \
    ISSUE_STAGE(sb + STB);                                                   \
    CP_COMMIT();                                                             \
    float acc[4][4][4];                                                      \
    _Pragma("unroll")                                                        \
    for (int i = 0; i < 4; ++i)                                              \
        _Pragma("unroll")                                                    \
        for (int j = 0; j < 4; ++j)                                          \
            _Pragma("unroll")                                                \
            for (int k = 0; k < 4; ++k) acc[i][j][k] = 0.f;                  \
    const int row_a = wm * 64 + (lane & 15);                                 \
    const uint32_t a_base = (uint32_t)row_a * GROW_B +                       \
        ((((uint32_t)lane >> 4) ^ ((uint32_t)row_a & 7)) << 4);              \
    const int row_b = wn * 32 + ((lane >> 4) << 3) + (lane & 7);             \
    const uint32_t b_base = (uint32_t)row_b * GROW_B +                       \
        (((((uint32_t)lane >> 3) & 1) ^ ((uint32_t)row_b & 7)) << 4);        \
    uint32_t cur_st = sb;                                                    \
    uint32_t iss_st = sb + 2 * STB;                                          \
    for (int t = 0; t < nt; ++t) {                                           \
        CP_WAIT1();                                                          \
        __syncthreads();                                                     \
        if (t + 2 < nt) ISSUE_STAGE(iss_st);                                 \
        CP_COMMIT();                                                         \
        const uint32_t pAs = cur_st, pBs = cur_st + GTILE_B;                 \
        _Pragma("unroll")                                                    \
        for (int k16 = 0; k16 < 4; ++k16) {                                  \
            const uint32_t kx = (uint32_t)(k16 << 5);                        \
            uint32_t fBh[2][4];                                              \
            _Pragma("unroll")                                                \
            for (int bt = 0; bt < 2; ++bt)                                   \
                ldsm_x4(fBh[bt], pBs + ((b_base + bt * (16 * GROW_B)) ^ kx));\
            _Pragma("unroll")                                                \
            for (int mt = 0; mt < 4; ++mt) {                                 \
                uint32_t fAh[4];                                             \
                ldsm_x4(fAh, pAs + ((a_base + mt * (16 * GROW_B)) ^ kx));    \
                _Pragma("unroll")                                            \
                for (int n8 = 0; n8 < 4; ++n8) {                             \
                    const uint32_t* bh = &fBh[n8 >> 1][(n8 & 1) << 1];       \
                    mma16816h(acc[mt][n8], fAh, bh);                         \
                }                                                            \
            }                                                                \
        }                                                                    \
        uint32_t nxt = cur_st + STB;                                         \
        if (nxt >= sb + 3 * STB) nxt = sb;                                   \
        cur_st = nxt;                                                        \
        nxt = iss_st + STB;                                                  \
        if (nxt >= sb + 3 * STB) nxt = sb;                                   \
        iss_st = nxt;                                                        \
    }

#define ISSUE_STAGE(st)                                                      \
    do {                                                                     \
        _Pragma("unroll")                                                    \
        for (int jj = 0; jj < 4; ++jj) {                                     \
            CP16((st) + ldst + jj * (32 * GROW_B), pA + jj * 32LL * ldaL);   \
            CP16((st) + GTILE_B + ldst + jj * (32 * GROW_B),                 \
                 pB + jj * 32LL * ldbL);                                     \
        }                                                                    \
        pA += 64; pB += 64;                                                  \
    } while (0)

// ---------------------------------------------------------------------------
// Generic NT fp16 GEMM (proj): C = Ah @ Bh + bias (fp32 out)
// ---------------------------------------------------------------------------
__global__ void __launch_bounds__(256, 2) gemm_f16(
    const __half* __restrict__ Ah, const __half* __restrict__ Bh,
    float* __restrict__ C, const float* __restrict__ bias,
    int K, int lda, int ldb, int ldc)
{
    extern __shared__ char smem[];
    __shared__ float s_bias[128];

    const int tid  = threadIdx.x;
    const int wid  = tid >> 5, lane = tid & 31;
    const int wm   = wid & 1;
    const int wn   = wid >> 1;
    const long long bm = (long long)blockIdx.y * 128;
    const long long bn = (long long)blockIdx.x * 128;
    const uint32_t sb = smem_u32(smem);

    if (tid < 128) s_bias[tid] = bias[bn + tid];

    GEMM_MAINLOOP(Ah, Bh, K, lda, ldb)

    #pragma unroll
    for (int mt = 0; mt < 4; ++mt) {
        const long long r = bm + wm * 64 + mt * 16 + (lane >> 2);
        float* row0 = C + r * ldc + bn + wn * 32;
        float* row1 = row0 + 8LL * ldc;
        #pragma unroll
        for (int n8 = 0; n8 < 4; ++n8) {
            const int c = n8 * 8 + ((lane & 3) << 1);
            const float b0 = s_bias[wn * 32 + c];
            const float b1 = s_bias[wn * 32 + c + 1];
            float2 v0, v1;
            v0.x = acc[mt][n8][0] + b0;
            v0.y = acc[mt][n8][1] + b1;
            v1.x = acc[mt][n8][2] + b0;
            v1.y = acc[mt][n8][3] + b1;
            *(float2*)(row0 + c) = v0;
            *(float2*)(row1 + c) = v1;
        }
    }
}

// ---------------------------------------------------------------------------
// QKV GEMM with fused RoPE (table-based) / V-transpose epilogue.
//   q/k (bn<4096):  RoPE via g_cos/g_sin, write fp16 hi to g_qkh
//   v (bn>=4096):   transpose, write fp16 hi to g_vth [(b,h),d,l]
// ---------------------------------------------------------------------------
__global__ void __launch_bounds__(256, 2) gemm_qkv(
    const __half* __restrict__ Ah, const __half* __restrict__ Bh,
    const float* __restrict__ bias)
{
    extern __shared__ char smem[];
    __shared__ float s_bias[128];

    const int tid  = threadIdx.x;
    const int wid  = tid >> 5, lane = tid & 31;
    const int wm   = wid & 1;
    const int wn   = wid >> 1;
    const long long bm = (long long)blockIdx.y * 128;
    const long long bn = (long long)blockIdx.x * 128;
    const uint32_t sb = smem_u32(smem);

    if (tid < 128) s_bias[tid] = bias[bn + tid];

    GEMM_MAINLOOP(Ah, Bh, EMB, EMB, EMB)

    // ---- stage biased fp32 tile into smem [128][129] ----
    __syncthreads();            // all warps done reading pipeline smem
    float* st = (float*)smem;
    #pragma unroll
    for (int mt = 0; mt < 4; ++mt) {
        const int rr = wm * 64 + mt * 16 + (lane >> 2);
        #pragma unroll
        for (int n8 = 0; n8 < 4; ++n8) {
            const int c = wn * 32 + n8 * 8 + ((lane & 3) << 1);
            const float b0 = s_bias[c], b1 = s_bias[c + 1];
            st[rr * 129 + c]           = acc[mt][n8][0] + b0;
            st[rr * 129 + c + 1]       = acc[mt][n8][1] + b1;
            st[(rr + 8) * 129 + c]     = acc[mt][n8][2] + b0;
            st[(rr + 8) * 129 + c + 1] = acc[mt][n8][3] + b1;
        }
    }
    __syncthreads();

    if (bn < 2 * EMB) {
        // ---- q or k head: RoPE via precomputed tables (hi only) ----
        #pragma unroll
        for (int it = 0; it < 32; ++it) {
            const int idx = it * 256 + tid;
            const int r = idx >> 6, j = idx & 63;
            const float v0 = st[r * 129 + j];
            const float v1 = st[r * 129 + j + 64];
            const long long tix = (bm + r) * 64 + j;
            const float cs = g_cos[tix];
            const float sn = g_sin[tix];
            const long long o = (bm + r) * (long long)E3 + bn;
            g_qkh[o + j]      = __float2half_rn(v0 * cs - v1 * sn);
            g_qkh[o + j + 64] = __float2half_rn(v1 * cs + v0 * sn);
        }
    } else {
        // ---- v head: transpose to [(b,h), d, l] ----
        const int hh = (int)((bn - 2 * EMB) >> 7);
        const int bb = (int)(bm >> 11);
        const int lbase = (int)(bm & (SEQ - 1));
        const long long vbase =
            ((long long)(bb * NH + hh) * HDIM) * SEQ + lbase;
        #pragma unroll
        for (int it = 0; it < 64; ++it) {
            const int idx = it * 256 + tid;
            const int d = idx >> 7, l = idx & 127;
            g_vth[vbase + (long long)d * SEQ + l] =
                __float2half_rn(st[l * 129 + d]);
        }
    }
}

// ---------------------------------------------------------------------------
// RoPE table prep: g_cos/g_sin[bl][j] = cos/sin(pos[bl] * 10000^(-j/64))
// ---------------------------------------------------------------------------
__global__ void __launch_bounds__(256) rope_prep_kernel(const int* __restrict__ pos)
{
    const int idx = blockIdx.x * 256 + threadIdx.x;   // BATCH*SEQ*64
    const int j  = idx & 63;
    const int bl = idx >> 6;
    const float p = (float)pos[bl];
    const float invf = expf(-(float)j * 0.14391156831212787f);
    float s, c;
    sincosf(p * invf, &s, &c);
    g_cos[idx] = c;
    g_sin[idx] = s;
}

// ---------------------------------------------------------------------------
// exp + pack 4 fp32 -> fp16 hi A-fragments, accumulate row sums
// ---------------------------------------------------------------------------
__device__ __forceinline__ void exp_pack4h(const float* s, float& lsum0,
                                           float& lsum1, uint32_t* ph)
{
    const float e0 = __expf(s[0] * SM_SCALE);
    const float e1 = __expf(s[1] * SM_SCALE);
    const float e2 = __expf(s[2] * SM_SCALE);
    const float e3 = __expf(s[3] * SM_SCALE);
    lsum0 += e0 + e1;
    lsum1 += e2 + e3;
    asm("cvt.rn.f16x2.f32 %0, %1, %2;" : "=r"(ph[0]) : "f"(e1), "f"(e0));
    asm("cvt.rn.f16x2.f32 %0, %1, %2;" : "=r"(ph[1]) : "f"(e3), "f"(e2));
}

// ---------------------------------------------------------------------------
// Fused flash attention, plain fp16 S and PV (Q hi, K hi, P hi, V hi).
// SMEM: Qh (32K) + K0|K1 (32K each) + V0|V1 (32K each) = 160 KB.
// (64B rows, chunk' = chunk ^ (row&3) ^ ((row>>2)&1) swizzle — unchanged.)
// ---------------------------------------------------------------------------
#define FA_SMEM (160 * 1024)

__global__ void __launch_bounds__(256) flash_kernel()
{
    extern __shared__ char smem[];
    const int z = blockIdx.y;
    const int b = z >> 4, h = z & 15;
    const int bq = blockIdx.x * 128;
    const int tid = threadIdx.x;
    const int wid = tid >> 5, lane = tid & 31;

    const uint32_t sb  = smem_u32(smem);
    const uint32_t BQh = sb;
    const uint32_t K0 = sb + 32768,  K1 = sb + 65536;
    const uint32_t V0 = sb + 98304,  V1 = sb + 131072;

    const int r0 = tid >> 2;
    const int cc = tid & 3;
    const uint32_t swsel = (uint32_t)((r0 & 3) ^ ((r0 >> 2) & 1));
    const uint32_t d0 = (uint32_t)r0 * 64 + ((cc ^ swsel) << 4);
    const uint32_t d1 = d0 + 64 * 64;

    const long long zq = (long long)b * SEQ * E3 + (long long)h * HDIM;
    const __half* Qh = g_qkh + zq;
    const __half* Kh = Qh + EMB;
    const __half* Vh = g_vth + (long long)z * HDIM * SEQ;

#define FA_LD1(buf, G, rowbase, ldx, colbase)                              \
    do { _Pragma("unroll")                                                 \
        for (int kc = 0; kc < 4; ++kc) {                                   \
            const long long off = ((long long)(rowbase) + r0) * (ldx)      \
                                  + (colbase) + kc * 32 + cc * 8;          \
            CP16((buf) + kc * 8192 + d0, (G) + off);                       \
            CP16((buf) + kc * 8192 + d1, (G) + off + 64LL * (ldx));        \
        }                                                                  \
    } while (0)

    // prologue: Q, K0, V0
    FA_LD1(BQh, Qh, bq, E3, 0);
    CP_COMMIT();
    FA_LD1(K0, Kh, 0, E3, 0);
    CP_COMMIT();
    FA_LD1(V0, Vh, 0, SEQ, 0);
    CP_COMMIT();

    CP_WAIT2();          // Q resident
    __syncthreads();

    const int row_a = wid * 16 + (lane & 15);
    const uint32_t swA = (uint32_t)((row_a & 3) ^ ((row_a >> 2) & 1));
    const uint32_t a_base =
        (uint32_t)row_a * 64 + ((((uint32_t)lane >> 4) ^ swA) << 4);
    uint32_t qfh[8][4];
    #pragma unroll
    for (int k16 = 0; k16 < 8; ++k16) {
        const uint32_t ad = (uint32_t)(k16 >> 1) * 8192 +
                            (a_base ^ ((uint32_t)(k16 & 1) << 5));
        ldsm_x4(qfh[k16], BQh + ad);
    }

    const int row_b = ((lane >> 4) << 3) + (lane & 7);
    const uint32_t swB = (uint32_t)((row_b & 3) ^ ((row_b >> 2) & 1));
    const uint32_t b_base =
        (uint32_t)row_b * 64 + (((((uint32_t)lane >> 3) & 1) ^ swB) << 4);

    float yacc[16][4];
    #pragma unroll
    for (int i = 0; i < 16; ++i)
        #pragma unroll
        for (int j = 0; j < 4; ++j) yacc[i][j] = 0.f;
    float lsum0 = 0.f, lsum1 = 0.f;

    for (int i = 0; i < 16; ++i) {
        const uint32_t curK = (i & 1) ? K1 : K0;
        const uint32_t curV = (i & 1) ? V1 : V0;

        CP_WAIT0();          // K_i, V_i resident
        __syncthreads();     // everyone done with buffers of iter i-1

        if (i < 15) {
            FA_LD1((i & 1) ? K0 : K1, Kh, 128 * (i + 1), E3, 0);
            CP_COMMIT();
            FA_LD1((i & 1) ? V0 : V1, Vh, 0, SEQ, 128 * (i + 1));
            CP_COMMIT();
        }

        // ---- S = Q K^T (fp16), nb-outer so exp interleaves ----
        uint32_t pfh[8][4];
        #pragma unroll
        for (int nb = 0; nb < 8; ++nb) {
            float s0[4] = {0.f, 0.f, 0.f, 0.f};
            float s1[4] = {0.f, 0.f, 0.f, 0.f};
            #pragma unroll
            for (int k16 = 0; k16 < 8; ++k16) {
                uint32_t fh[4];
                const uint32_t ad = (uint32_t)(k16 >> 1) * 8192 +
                    ((b_base + (uint32_t)nb * 1024u) ^ ((uint32_t)(k16 & 1) << 5));
                ldsm_x4(fh, curK + ad);
                mma16816h(s0, qfh[k16], fh);
                mma16816h(s1, qfh[k16], fh + 2);
            }
            exp_pack4h(s0, lsum0, lsum1, &pfh[nb][0]);
            exp_pack4h(s1, lsum0, lsum1, &pfh[nb][2]);
        }

        // ---- y += P V (fp16) ----
        #pragma unroll
        for (int k16 = 0; k16 < 8; ++k16) {
            #pragma unroll
            for (int nb = 0; nb < 8; ++nb) {
                uint32_t fv[4];
                const uint32_t ad = (uint32_t)(k16 >> 1) * 8192 +
                    ((b_base + (uint32_t)nb * 1024u) ^ ((uint32_t)(k16 & 1) << 5));
                ldsm_x4(fv, curV + ad);
                mma16816h(yacc[2 * nb],     pfh[k16], fv);
                mma16816h(yacc[2 * nb + 1], pfh[k16], fv + 2);
            }
        }
    }
#undef FA_LD1

    // ---- normalize + store (hi only) ----
    lsum0 += __shfl_xor_sync(0xffffffffu, lsum0, 1);
    lsum0 += __shfl_xor_sync(0xffffffffu, lsum0, 2);
    lsum1 += __shfl_xor_sync(0xffffffffu, lsum1, 1);
    lsum1 += __shfl_xor_sync(0xffffffffu, lsum1, 2);
    const float inv0 = 1.0f / lsum0;
    const float inv1 = 1.0f / lsum1;

    const int q0 = bq + wid * 16 + (lane >> 2);
    const long long ob = (long long)b * SEQ * EMB + (long long)h * HDIM;
    #pragma unroll
    for (int T = 0; T < 16; ++T) {
        const int dcol = T * 8 + ((lane & 3) << 1);
        __half2 hh0, hh1;
        hh0.x = __float2half_rn(yacc[T][0] * inv0);
        hh0.y = __float2half_rn(yacc[T][1] * inv0);
        hh1.x = __float2half_rn(yacc[T][2] * inv1);
        hh1.y = __float2half_rn(yacc[T][3] * inv1);
        const long long o0 = ob + (long long)q0 * EMB + dcol;
        const long long o1 = o0 + 8LL * EMB;
        *(__half2*)(g_yh + o0) = hh0;
        *(__half2*)(g_yh + o1) = hh1;
    }
}

// ---------------------------------------------------------------------------
// fp32 -> fp16 convert, flat, 4 elems/thread
// ---------------------------------------------------------------------------
struct h4 { __half x, y, z, w; };

__global__ void __launch_bounds__(256) conv_kernel(
    const float* __restrict__ s, __half* __restrict__ h, int n4)
{
    const int i = blockIdx.x * 256 + threadIdx.x;
    if (i >= n4) return;
    const float4 v = ((const float4*)s)[i];
    h4 hh;
    hh.x = __float2half_rn(v.x);
    hh.y = __float2half_rn(v.y);
    hh.z = __float2half_rn(v.z);
    hh.w = __float2half_rn(v.w);
    ((h4*)h)[i] = hh;
}

// ---------------------------------------------------------------------------
// Transpose (hi only): src [K,N] fp32 row-major -> dst [N,K] fp16
// ---------------------------------------------------------------------------
__global__ void __launch_bounds__(256) tsplit_kernel(
    const float* __restrict__ s, __half* __restrict__ h, int K, int N)
{
    __shared__ float tile[32][33];
    const int tx = threadIdx.x, ty = threadIdx.y;
    const int n0 = blockIdx.x * 32, k0 = blockIdx.y * 32;
    #pragma unroll
    for (int j = 0; j < 32; j += 8)
        tile[ty + j][tx] = s[(long long)(k0 + ty + j) * N + n0 + tx];
    __syncthreads();
    #pragma unroll
    for (int j = 0; j < 32; j += 8) {
        const float v = tile[tx][ty + j];
        const long long o = (long long)(n0 + ty + j) * K + k0 + tx;
        h[o] = __float2half_rn(v);
    }
}

// ---------------------------------------------------------------------------
// Launch sequence
// ---------------------------------------------------------------------------
extern "C" void kernel_launch(void* const* d_in, const int* in_sizes, int n_in,
                              void* d_out, int out_size)
{
    const float* x      = (const float*)d_in[0];
    const int*   pos    = (const int*)  d_in[1];
    const float* W_attn = (const float*)d_in[2];
    const float* b_attn = (const float*)d_in[3];
    const float* W_proj = (const float*)d_in[4];
    const float* b_proj = (const float*)d_in[5];
    float* out = (float*)d_out;

    __half *xh, *wah, *yh, *wph;
    cudaGetSymbolAddress((void**)&xh,  g_xh);
    cudaGetSymbolAddress((void**)&wah, g_wah);
    cudaGetSymbolAddress((void**)&yh,  g_yh);
    cudaGetSymbolAddress((void**)&wph, g_wph);

    cudaFuncSetAttribute(gemm_f16,
                         cudaFuncAttributeMaxDynamicSharedMemorySize, GSMEM);
    cudaFuncSetAttribute(gemm_qkv,
                         cudaFuncAttributeMaxDynamicSharedMemorySize, GSMEM);
    cudaFuncSetAttribute(flash_kernel,
                         cudaFuncAttributeMaxDynamicSharedMemorySize, FA_SMEM);

    const dim3 tb(32, 8, 1);

    // 0. conversions + RoPE tables
    rope_prep_kernel<<<(BATCH * SEQ * 64) / 256, 256>>>(pos);
    conv_kernel<<<(BATCH * SEQ * EMB / 4 + 255) / 256, 256>>>(x, xh,
                                                              BATCH * SEQ * EMB / 4);
    tsplit_kernel<<<dim3(E3 / 32, EMB / 32, 1), tb>>>(W_attn, wah, EMB, E3);
    tsplit_kernel<<<dim3(EMB / 32, EMB / 32, 1), tb>>>(W_proj, wph, EMB, EMB);

    // 1. qkv GEMM (single product, BK=64) + fused bias/RoPE/V-transpose
    gemm_qkv<<<dim3(E3 / 128, (BATCH * SEQ) / 128, 1), 256, GSMEM>>>(
        xh, wah, b_attn);

    // 2. fused attention (fp16) -> yh
    flash_kernel<<<dim3(SEQ / 128, BATCH * NH, 1), 256, FA_SMEM>>>();

    // 3. out = y @ W_proj + b (single product, BK=64)
    gemm_f16<<<dim3(EMB / 128, (BATCH * SEQ) / 128, 1), 256, GSMEM>>>(
        yh, wph, out, b_proj, EMB, EMB, EMB, EMB);
}

// round 14
// speedup vs baseline: 1.9089x; 1.0786x over previous
#include <cuda_runtime.h>
#include <cuda_fp16.h>
#include <cstdint>
#include <math.h>

// Problem constants
#define BATCH 2
#define SEQ   2048
#define EMB   2048
#define NH    16
#define HDIM  128
#define E3    6144

#define SM_SCALE 0.08838834764831845f

// ---------------------------------------------------------------------------
// Scratch (__device__ globals; allocation-free rule)
// ---------------------------------------------------------------------------
__device__ __half g_xh[(size_t)BATCH * SEQ * EMB];
__device__ __half g_wah[(size_t)E3 * EMB];                         // W_attn^T hi
__device__ __half g_qkh[(size_t)BATCH * SEQ * E3];                 // q hi | k hi
__device__ __half g_vth[(size_t)BATCH * NH * HDIM * SEQ];          // V^T hi
__device__ __half g_yh[(size_t)BATCH * SEQ * EMB];
__device__ __half g_wph[(size_t)EMB * EMB];                        // W_proj^T hi
__device__ float  g_cos[(size_t)BATCH * SEQ * 64];                 // RoPE tables
__device__ float  g_sin[(size_t)BATCH * SEQ * 64];

// ---------------------------------------------------------------------------
// PTX helpers (arch-generic: cp.async, ldmatrix, mma.sync)
// ---------------------------------------------------------------------------
__device__ __forceinline__ uint32_t smem_u32(const void* p) {
    uint32_t a;
    asm("{ .reg .u64 t; cvta.to.shared.u64 t, %1; cvt.u32.u64 %0, t; }"
        : "=r"(a) : "l"(p));
    return a;
}
#define CP16(dst, src) \
    asm volatile("cp.async.cg.shared.global [%0], [%1], 16;" :: "r"(dst), "l"(src))
#define CP_COMMIT() asm volatile("cp.async.commit_group;" ::: "memory")
#define CP_WAIT0()  asm volatile("cp.async.wait_group 0;" ::: "memory")
#define CP_WAIT1()  asm volatile("cp.async.wait_group 1;" ::: "memory")
#define CP_WAIT2()  asm volatile("cp.async.wait_group 2;" ::: "memory")

__device__ __forceinline__ void ldsm_x4(uint32_t* r, uint32_t a) {
    asm volatile("ldmatrix.sync.aligned.m8n8.x4.shared.b16 {%0,%1,%2,%3}, [%4];"
        : "=r"(r[0]), "=r"(r[1]), "=r"(r[2]), "=r"(r[3]) : "r"(a));
}
__device__ __forceinline__ void mma16816h(float* d, const uint32_t* a,
                                          const uint32_t* b) {
    asm volatile(
        "mma.sync.aligned.m16n8k16.row.col.f32.f16.f16.f32 "
        "{%0,%1,%2,%3}, {%4,%5,%6,%7}, {%8,%9}, {%0,%1,%2,%3};"
        : "+f"(d[0]), "+f"(d[1]), "+f"(d[2]), "+f"(d[3])
        : "r"(a[0]), "r"(a[1]), "r"(a[2]), "r"(a[3]), "r"(b[0]), "r"(b[1]));
}

// ---------------------------------------------------------------------------
// GEMM tile geometry (BK=64): 128 rows x 64 fp16 = 128B rows.
// Swizzle: chunk' = chunk ^ (row & 7).
// ---------------------------------------------------------------------------
#define GROW_B  128
#define GTILE_B 16384
#define STB     (2 * GTILE_B)        // stage bytes (Ah, Bh) = 32 KB
#define GSMEM   (3 * STB)            // 96 KB; also >= 128*129*4 epilogue staging

// ===========================================================================
// Shared GEMM mainloop (single product Ah*Bh, BK=64): computes acc[4][4][4]
// ===========================================================================
#define GEMM_MAINLOOP(Ah, Bh, K, lda, ldb)                                   \
    const long long ldaL = (lda), ldbL = (ldb);                              \
    const int lr0 = tid >> 3;                                                \
    const int lc  = tid & 7;                                                 \
    const uint32_t ldst =                                                    \
        (uint32_t)lr0 * GROW_B + (((uint32_t)lc ^ (lr0 & 7)) << 4);          \
    const __half* pA = (Ah) + (bm + lr0) * ldaL + lc * 8;                    \
    const __half* pB = (Bh) + (bn + lr0) * ldbL + lc * 8;                    \
    const int nt = (K) >> 6;                                                 \
    ISSUE_STAGE(sb);                                                         \
    CP_COMMIT();                                                             \
    ISSUE_STAGE(sb + STB);                                                   \
    CP_COMMIT();                                                             \
    float acc[4][4][4];                                                      \
    _Pragma("unroll")                                                        \
    for (int i = 0; i < 4; ++i)                                              \
        _Pragma("unroll")                                                    \
        for (int j = 0; j < 4; ++j)                                          \
            _Pragma("unroll")                                                \
            for (int k = 0; k < 4; ++k) acc[i][j][k] = 0.f;                  \
    const int row_a = wm * 64 + (lane & 15);                                 \
    const uint32_t a_base = (uint32_t)row_a * GROW_B +                       \
        ((((uint32_t)lane >> 4) ^ ((uint32_t)row_a & 7)) << 4);              \
    const int row_b = wn * 32 + ((lane >> 4) << 3) + (lane & 7);             \
    const uint32_t b_base = (uint32_t)row_b * GROW_B +                       \
        (((((uint32_t)lane >> 3) & 1) ^ ((uint32_t)row_b & 7)) << 4);        \
    uint32_t cur_st = sb;                                                    \
    uint32_t iss_st = sb + 2 * STB;                                          \
    for (int t = 0; t < nt; ++t) {                                           \
        CP_WAIT1();                                                          \
        __syncthreads();                                                     \
        if (t + 2 < nt) ISSUE_STAGE(iss_st);                                 \
        CP_COMMIT();                                                         \
        const uint32_t pAs = cur_st, pBs = cur_st + GTILE_B;                 \
        _Pragma("unroll")                                                    \
        for (int k16 = 0; k16 < 4; ++k16) {                                  \
            const uint32_t kx = (uint32_t)(k16 << 5);                        \
            uint32_t fBh[2][4];                                              \
            _Pragma("unroll")                                                \
            for (int bt = 0; bt < 2; ++bt)                                   \
                ldsm_x4(fBh[bt], pBs + ((b_base + bt * (16 * GROW_B)) ^ kx));\
            _Pragma("unroll")                                                \
            for (int mt = 0; mt < 4; ++mt) {                                 \
                uint32_t fAh[4];                                             \
                ldsm_x4(fAh, pAs + ((a_base + mt * (16 * GROW_B)) ^ kx));    \
                _Pragma("unroll")                                            \
                for (int n8 = 0; n8 < 4; ++n8) {                             \
                    const uint32_t* bh = &fBh[n8 >> 1][(n8 & 1) << 1];       \
                    mma16816h(acc[mt][n8], fAh, bh);                         \
                }                                                            \
            }                                                                \
        }                                                                    \
        uint32_t nxt = cur_st + STB;                                         \
        if (nxt >= sb + 3 * STB) nxt = sb;                                   \
        cur_st = nxt;                                                        \
        nxt = iss_st + STB;                                                  \
        if (nxt >= sb + 3 * STB) nxt = sb;                                   \
        iss_st = nxt;                                                        \
    }

#define ISSUE_STAGE(st)                                                      \
    do {                                                                     \
        _Pragma("unroll")                                                    \
        for (int jj = 0; jj < 4; ++jj) {                                     \
            CP16((st) + ldst + jj * (32 * GROW_B), pA + jj * 32LL * ldaL);   \
            CP16((st) + GTILE_B + ldst + jj * (32 * GROW_B),                 \
                 pB + jj * 32LL * ldbL);                                     \
        }                                                                    \
        pA += 64; pB += 64;                                                  \
    } while (0)

// ---------------------------------------------------------------------------
// Generic NT fp16 GEMM (proj): C = Ah @ Bh + bias (fp32 out)
// ---------------------------------------------------------------------------
__global__ void __launch_bounds__(256, 2) gemm_f16(
    const __half* __restrict__ Ah, const __half* __restrict__ Bh,
    float* __restrict__ C, const float* __restrict__ bias,
    int K, int lda, int ldb, int ldc)
{
    extern __shared__ char smem[];
    __shared__ float s_bias[128];

    const int tid  = threadIdx.x;
    const int wid  = tid >> 5, lane = tid & 31;
    const int wm   = wid & 1;
    const int wn   = wid >> 1;
    const long long bm = (long long)blockIdx.y * 128;
    const long long bn = (long long)blockIdx.x * 128;
    const uint32_t sb = smem_u32(smem);

    if (tid < 128) s_bias[tid] = bias[bn + tid];

    GEMM_MAINLOOP(Ah, Bh, K, lda, ldb)

    #pragma unroll
    for (int mt = 0; mt < 4; ++mt) {
        const long long r = bm + wm * 64 + mt * 16 + (lane >> 2);
        float* row0 = C + r * ldc + bn + wn * 32;
        float* row1 = row0 + 8LL * ldc;
        #pragma unroll
        for (int n8 = 0; n8 < 4; ++n8) {
            const int c = n8 * 8 + ((lane & 3) << 1);
            const float b0 = s_bias[wn * 32 + c];
            const float b1 = s_bias[wn * 32 + c + 1];
            float2 v0, v1;
            v0.x = acc[mt][n8][0] + b0;
            v0.y = acc[mt][n8][1] + b1;
            v1.x = acc[mt][n8][2] + b0;
            v1.y = acc[mt][n8][3] + b1;
            *(float2*)(row0 + c) = v0;
            *(float2*)(row1 + c) = v1;
        }
    }
}

// ---------------------------------------------------------------------------
// QKV GEMM with fused RoPE (table-based) / V-transpose epilogue.
// ---------------------------------------------------------------------------
__global__ void __launch_bounds__(256, 2) gemm_qkv(
    const __half* __restrict__ Ah, const __half* __restrict__ Bh,
    const float* __restrict__ bias)
{
    extern __shared__ char smem[];
    __shared__ float s_bias[128];

    const int tid  = threadIdx.x;
    const int wid  = tid >> 5, lane = tid & 31;
    const int wm   = wid & 1;
    const int wn   = wid >> 1;
    const long long bm = (long long)blockIdx.y * 128;
    const long long bn = (long long)blockIdx.x * 128;
    const uint32_t sb = smem_u32(smem);

    if (tid < 128) s_bias[tid] = bias[bn + tid];

    GEMM_MAINLOOP(Ah, Bh, EMB, EMB, EMB)

    // ---- stage biased fp32 tile into smem [128][129] ----
    __syncthreads();
    float* st = (float*)smem;
    #pragma unroll
    for (int mt = 0; mt < 4; ++mt) {
        const int rr = wm * 64 + mt * 16 + (lane >> 2);
        #pragma unroll
        for (int n8 = 0; n8 < 4; ++n8) {
            const int c = wn * 32 + n8 * 8 + ((lane & 3) << 1);
            const float b0 = s_bias[c], b1 = s_bias[c + 1];
            st[rr * 129 + c]           = acc[mt][n8][0] + b0;
            st[rr * 129 + c + 1]       = acc[mt][n8][1] + b1;
            st[(rr + 8) * 129 + c]     = acc[mt][n8][2] + b0;
            st[(rr + 8) * 129 + c + 1] = acc[mt][n8][3] + b1;
        }
    }
    __syncthreads();

    if (bn < 2 * EMB) {
        #pragma unroll
        for (int it = 0; it < 32; ++it) {
            const int idx = it * 256 + tid;
            const int r = idx >> 6, j = idx & 63;
            const float v0 = st[r * 129 + j];
            const float v1 = st[r * 129 + j + 64];
            const long long tix = (bm + r) * 64 + j;
            const float cs = g_cos[tix];
            const float sn = g_sin[tix];
            const long long o = (bm + r) * (long long)E3 + bn;
            g_qkh[o + j]      = __float2half_rn(v0 * cs - v1 * sn);
            g_qkh[o + j + 64] = __float2half_rn(v1 * cs + v0 * sn);
        }
    } else {
        const int hh = (int)((bn - 2 * EMB) >> 7);
        const int bb = (int)(bm >> 11);
        const int lbase = (int)(bm & (SEQ - 1));
        const long long vbase =
            ((long long)(bb * NH + hh) * HDIM) * SEQ + lbase;
        #pragma unroll
        for (int it = 0; it < 64; ++it) {
            const int idx = it * 256 + tid;
            const int d = idx >> 7, l = idx & 127;
            g_vth[vbase + (long long)d * SEQ + l] =
                __float2half_rn(st[l * 129 + d]);
        }
    }
}

// ---------------------------------------------------------------------------
// Merged prep kernel: rope tables | x convert | W_attn^T | W_proj^T
// Block ranges: [0,1024) rope, [1024,9216) conv, [9216,21504) wa, [21504,25600) wp
// ---------------------------------------------------------------------------
__global__ void __launch_bounds__(256) prep_kernel(
    const float* __restrict__ x, const float* __restrict__ W_attn,
    const float* __restrict__ W_proj, const int* __restrict__ pos)
{
    const int bx = blockIdx.x;
    const int tid = threadIdx.x;

    if (bx < 1024) {
        // RoPE tables
        const int idx = bx * 256 + tid;
        const int j  = idx & 63;
        const int bl = idx >> 6;
        const float p = (float)pos[bl];
        const float invf = expf(-(float)j * 0.14391156831212787f);
        float s, c;
        sincosf(p * invf, &s, &c);
        g_cos[idx] = c;
        g_sin[idx] = s;
        return;
    }
    if (bx < 9216) {
        // x fp32 -> fp16 (float4 per thread)
        const int i = (bx - 1024) * 256 + tid;
        const float4 v = ((const float4*)x)[i];
        __half2 h0, h1;
        h0.x = __float2half_rn(v.x); h0.y = __float2half_rn(v.y);
        h1.x = __float2half_rn(v.z); h1.y = __float2half_rn(v.w);
        ((__half2*)g_xh)[2 * i]     = h0;
        ((__half2*)g_xh)[2 * i + 1] = h1;
        return;
    }
    // transpose-convert weights
    __shared__ float tile[32][33];
    const int tx = tid & 31, ty = tid >> 5;
    const float* src;
    __half* dst;
    int Kd, Nd, n0, k0;
    if (bx < 21504) {
        const int f = bx - 9216;            // 192 x 64
        src = W_attn; dst = g_wah; Kd = EMB; Nd = E3;
        n0 = (f % 192) * 32; k0 = (f / 192) * 32;
    } else {
        const int f = bx - 21504;           // 64 x 64
        src = W_proj; dst = g_wph; Kd = EMB; Nd = EMB;
        n0 = (f % 64) * 32; k0 = (f / 64) * 32;
    }
    #pragma unroll
    for (int j = 0; j < 32; j += 8)
        tile[ty + j][tx] = src[(long long)(k0 + ty + j) * Nd + n0 + tx];
    __syncthreads();
    #pragma unroll
    for (int j = 0; j < 32; j += 8) {
        const float v = tile[tx][ty + j];
        const long long o = (long long)(n0 + ty + j) * Kd + k0 + tx;
        dst[o] = __float2half_rn(v);
    }
}

// ---------------------------------------------------------------------------
// exp + pack 4 fp32 -> fp16 hi A-fragments, accumulate row sums
// ---------------------------------------------------------------------------
__device__ __forceinline__ void exp_pack4h(const float* s, float& lsum0,
                                           float& lsum1, uint32_t* ph)
{
    const float e0 = __expf(s[0] * SM_SCALE);
    const float e1 = __expf(s[1] * SM_SCALE);
    const float e2 = __expf(s[2] * SM_SCALE);
    const float e3 = __expf(s[3] * SM_SCALE);
    lsum0 += e0 + e1;
    lsum1 += e2 + e3;
    asm("cvt.rn.f16x2.f32 %0, %1, %2;" : "=r"(ph[0]) : "f"(e1), "f"(e0));
    asm("cvt.rn.f16x2.f32 %0, %1, %2;" : "=r"(ph[1]) : "f"(e3), "f"(e2));
}

// ---------------------------------------------------------------------------
// Fused flash attention, fp16, 512 threads, 256 q-rows per CTA.
// 16 warps (4/SMSP), grid (8, 32) = 256 CTAs. Per-chunk fused S->exp->PV.
// SMEM: Q0|Q1 (32K each) + K0|K1 (32K each) + V0|V1 (32K each) = 192 KB.
// ---------------------------------------------------------------------------
#define FA_SMEM (192 * 1024)

__global__ void __launch_bounds__(512) flash_kernel()
{
    extern __shared__ char smem[];
    const int z = blockIdx.y;
    const int b = z >> 4, h = z & 15;
    const int bq = blockIdx.x * 256;
    const int tid = threadIdx.x;
    const int wid = tid >> 5, lane = tid & 31;

    const uint32_t sb = smem_u32(smem);
    const uint32_t BQ0 = sb,            BQ1 = sb + 32768;
    const uint32_t K0  = sb + 65536,    K1  = sb + 98304;
    const uint32_t V0  = sb + 131072,   V1  = sb + 163840;

    // loader mapping: 512 threads, 4 CP16 each per 32KB buffer
    const int lr = tid >> 2;            // 0..127
    const int cc = tid & 3;
    const uint32_t swsel = (uint32_t)((lr & 3) ^ ((lr >> 2) & 1));
    const uint32_t d0 = (uint32_t)lr * 64 + ((cc ^ swsel) << 4);

    const long long zq = (long long)b * SEQ * E3 + (long long)h * HDIM;
    const __half* Qh = g_qkh + zq;
    const __half* Kh = Qh + EMB;
    const __half* Vh = g_vth + (long long)z * HDIM * SEQ;

#define FA_LD1(buf, G, rowbase, ldx, colbase)                              \
    do { _Pragma("unroll")                                                 \
        for (int kc = 0; kc < 4; ++kc) {                                   \
            const long long off = ((long long)(rowbase) + lr) * (ldx)      \
                                  + (colbase) + kc * 32 + cc * 8;          \
            CP16((buf) + kc * 8192 + d0, (G) + off);                       \
        }                                                                  \
    } while (0)

    // prologue: Q (two halves), K0, V0
    FA_LD1(BQ0, Qh, bq, E3, 0);
    FA_LD1(BQ1, Qh, bq + 128, E3, 0);
    CP_COMMIT();
    FA_LD1(K0, Kh, 0, E3, 0);
    CP_COMMIT();
    FA_LD1(V0, Vh, 0, SEQ, 0);
    CP_COMMIT();

    CP_WAIT2();          // Q resident
    __syncthreads();

    // Q fragments: warp wid owns q rows bq + wid*16 .. +15
    const int inner = (wid & 7) * 16 + (lane & 15);
    const uint32_t qbuf = (wid < 8) ? BQ0 : BQ1;
    const uint32_t swA = (uint32_t)((inner & 3) ^ ((inner >> 2) & 1));
    const uint32_t a_base =
        (uint32_t)inner * 64 + ((((uint32_t)lane >> 4) ^ swA) << 4);
    uint32_t qfh[8][4];
    #pragma unroll
    for (int k16 = 0; k16 < 8; ++k16) {
        const uint32_t ad = (uint32_t)(k16 >> 1) * 8192 +
                            (a_base ^ ((uint32_t)(k16 & 1) << 5));
        ldsm_x4(qfh[k16], qbuf + ad);
    }

    const int row_b = ((lane >> 4) << 3) + (lane & 7);
    const uint32_t swB = (uint32_t)((row_b & 3) ^ ((row_b >> 2) & 1));
    const uint32_t b_base =
        (uint32_t)row_b * 64 + (((((uint32_t)lane >> 3) & 1) ^ swB) << 4);

    float yacc[16][4];
    #pragma unroll
    for (int i = 0; i < 16; ++i)
        #pragma unroll
        for (int j = 0; j < 4; ++j) yacc[i][j] = 0.f;
    float lsum0 = 0.f, lsum1 = 0.f;

    for (int i = 0; i < 16; ++i) {
        const uint32_t curK = (i & 1) ? K1 : K0;
        const uint32_t curV = (i & 1) ? V1 : V0;

        CP_WAIT0();
        __syncthreads();

        if (i < 15) {
            FA_LD1((i & 1) ? K0 : K1, Kh, 128 * (i + 1), E3, 0);
            CP_COMMIT();
            FA_LD1((i & 1) ? V0 : V1, Vh, 0, SEQ, 128 * (i + 1));
            CP_COMMIT();
        }

        // ---- per-chunk fused: S_c -> exp_c -> PV_c ----
        #pragma unroll
        for (int c = 0; c < 8; ++c) {
            float s0[4] = {0.f, 0.f, 0.f, 0.f};
            float s1[4] = {0.f, 0.f, 0.f, 0.f};
            #pragma unroll
            for (int k16 = 0; k16 < 8; ++k16) {
                uint32_t fh[4];
                const uint32_t ad = (uint32_t)(k16 >> 1) * 8192 +
                    ((b_base + (uint32_t)c * 1024u) ^ ((uint32_t)(k16 & 1) << 5));
                ldsm_x4(fh, curK + ad);
                mma16816h(s0, qfh[k16], fh);
                mma16816h(s1, qfh[k16], fh + 2);
            }
            uint32_t ph[4];
            exp_pack4h(s0, lsum0, lsum1, &ph[0]);
            exp_pack4h(s1, lsum0, lsum1, &ph[2]);
            #pragma unroll
            for (int nb = 0; nb < 8; ++nb) {
                uint32_t fv[4];
                const uint32_t ad = (uint32_t)(c >> 1) * 8192 +
                    ((b_base + (uint32_t)nb * 1024u) ^ ((uint32_t)(c & 1) << 5));
                ldsm_x4(fv, curV + ad);
                mma16816h(yacc[2 * nb],     ph, fv);
                mma16816h(yacc[2 * nb + 1], ph, fv + 2);
            }
        }
    }
#undef FA_LD1

    // ---- normalize + store (hi only) ----
    lsum0 += __shfl_xor_sync(0xffffffffu, lsum0, 1);
    lsum0 += __shfl_xor_sync(0xffffffffu, lsum0, 2);
    lsum1 += __shfl_xor_sync(0xffffffffu, lsum1, 1);
    lsum1 += __shfl_xor_sync(0xffffffffu, lsum1, 2);
    const float inv0 = 1.0f / lsum0;
    const float inv1 = 1.0f / lsum1;

    const int q0 = bq + wid * 16 + (lane >> 2);
    const long long ob = (long long)b * SEQ * EMB + (long long)h * HDIM;
    #pragma unroll
    for (int T = 0; T < 16; ++T) {
        const int dcol = T * 8 + ((lane & 3) << 1);
        __half2 hh0, hh1;
        hh0.x = __float2half_rn(yacc[T][0] * inv0);
        hh0.y = __float2half_rn(yacc[T][1] * inv0);
        hh1.x = __float2half_rn(yacc[T][2] * inv1);
        hh1.y = __float2half_rn(yacc[T][3] * inv1);
        const long long o0 = ob + (long long)q0 * EMB + dcol;
        const long long o1 = o0 + 8LL * EMB;
        *(__half2*)(g_yh + o0) = hh0;
        *(__half2*)(g_yh + o1) = hh1;
    }
}

// ---------------------------------------------------------------------------
// Launch sequence
// ---------------------------------------------------------------------------
extern "C" void kernel_launch(void* const* d_in, const int* in_sizes, int n_in,
                              void* d_out, int out_size)
{
    const float* x      = (const float*)d_in[0];
    const int*   pos    = (const int*)  d_in[1];
    const float* W_attn = (const float*)d_in[2];
    const float* b_attn = (const float*)d_in[3];
    const float* W_proj = (const float*)d_in[4];
    const float* b_proj = (const float*)d_in[5];
    float* out = (float*)d_out;

    __half *xh, *wah, *yh, *wph;
    cudaGetSymbolAddress((void**)&xh,  g_xh);
    cudaGetSymbolAddress((void**)&wah, g_wah);
    cudaGetSymbolAddress((void**)&yh,  g_yh);
    cudaGetSymbolAddress((void**)&wph, g_wph);

    cudaFuncSetAttribute(gemm_f16,
                         cudaFuncAttributeMaxDynamicSharedMemorySize, GSMEM);
    cudaFuncSetAttribute(gemm_qkv,
                         cudaFuncAttributeMaxDynamicSharedMemorySize, GSMEM);
    cudaFuncSetAttribute(flash_kernel,
                         cudaFuncAttributeMaxDynamicSharedMemorySize, FA_SMEM);

    // 0. merged prep: rope tables + x convert + weight transposes
    prep_kernel<<<25600, 256>>>(x, W_attn, W_proj, pos);

    // 1. qkv GEMM (single product, BK=64) + fused bias/RoPE/V-transpose
    gemm_qkv<<<dim3(E3 / 128, (BATCH * SEQ) / 128, 1), 256, GSMEM>>>(
        xh, wah, b_attn);

    // 2. fused attention (fp16, 512 thr, 256 q-rows/CTA) -> yh
    flash_kernel<<<dim3(SEQ / 256, BATCH * NH, 1), 512, FA_SMEM>>>();

    // 3. out = y @ W_proj + b (single product, BK=64)
    gemm_f16<<<dim3(EMB / 128, (BATCH * SEQ) / 128, 1), 256, GSMEM>>>(
        yh, wph, out, b_proj, EMB, EMB, EMB, EMB);
}